// round 12
// baseline (speedup 1.0000x reference)
#include <cuda_runtime.h>
#include <cuda_bf16.h>
#include <cstdint>

// ---------------- problem constants ----------------
#define B_     16
#define L_     8192
#define IN_    57
#define DM     64
#define DS     32
#define HD     32
#define NH     4
#define DI     128          // EXP*DM
#define DPROJ  324          // 2*DI + 2*DS + NH
#define NL     2
#define OUT_   6
#define Q      64           // chunk length
#define NCH    (L_ / Q)     // 128 chunks
#define NSEG   16           // scan segments
#define CPS    (NCH / NSEG) // 8 chunks per segment
#define BL     (B_ * L_)    // 131072 rows

// ---------------- scratch (device globals; allocation-free) ----------------
__device__ float g_h [BL * DM];
__device__ float g_X [BL * DI];
__device__ float g_Z [BL * DI];
__device__ float g_Bm[BL * DS];
__device__ float g_Cm[BL * DS];
__device__ float g_dt[BL * NH];
__device__ float g_la[BL * NH];
__device__ float g_Sd[B_ * NH * NCH * HD * DS];    // chunk delta states
__device__ float g_h0[B_ * NH * NCH * HD * DS];    // segment-local entry states
__device__ float g_aQ[B_ * NH * NCH];              // chunk total decay
__device__ float g_segS[B_ * NH * NSEG * HD * DS]; // segment delta states
__device__ float g_segA[B_ * NH * NSEG];           // segment decay product
__device__ float g_segIn[B_ * NH * NSEG * HD * DS];// segment entry states
__device__ double g_pool[B_ * 16 * DM];

// ---------------- helpers ----------------
__device__ __forceinline__ float siluf(float v) { return v / (1.f + __expf(-v)); }
__device__ __forceinline__ float softplusf(float v) { return (v > 20.f) ? v : log1pf(__expf(v)); }

__device__ __forceinline__ unsigned cvt_tf32(float f) {
    unsigned u; asm("cvt.rna.tf32.f32 %0, %1;" : "=r"(u) : "f"(f)); return u;
}
__device__ __forceinline__ void sp32(float v, unsigned& h, unsigned& l) {
    h = cvt_tf32(v);
    l = cvt_tf32(v - __uint_as_float(h));
}
__device__ __forceinline__ void mma_tf32(float* d, const unsigned* a, const unsigned* b) {
    asm volatile("mma.sync.aligned.m16n8k8.row.col.f32.tf32.tf32.f32 "
                 "{%0,%1,%2,%3},{%4,%5,%6,%7},{%8,%9},{%0,%1,%2,%3};"
                 : "+f"(d[0]), "+f"(d[1]), "+f"(d[2]), "+f"(d[3])
                 : "r"(a[0]), "r"(a[1]), "r"(a[2]), "r"(a[3]),
                   "r"(b[0]), "r"(b[1]));
}

// ================= K1: linear_in  h = x @ W_in + b_in =================
__global__ void k_linear_in(const float* __restrict__ x,
                            const float* __restrict__ W,
                            const float* __restrict__ bias) {
    const int row0 = blockIdx.x * 16;
    __shared__ float sx[16][IN_ + 1];
    const int tid = threadIdx.x;
    for (int idx = tid; idx < 16 * IN_; idx += 256) {
        int r = idx / IN_, k = idx % IN_;
        sx[r][k] = x[(size_t)(row0 + r) * IN_ + k];
    }
    __syncthreads();
    const int c = tid & 63, q = tid >> 6;
    float bc = bias[c];
    float acc[4] = {bc, bc, bc, bc};
    for (int k = 0; k < IN_; k++) {
        float wv = __ldg(&W[k * DM + c]);
#pragma unroll
        for (int j = 0; j < 4; j++) acc[j] += sx[q * 4 + j][k] * wv;
    }
#pragma unroll
    for (int j = 0; j < 4; j++)
        g_h[(size_t)(row0 + q * 4 + j) * DM + c] = acc[j];
}

// ================= K2: in_proj via tf32 MMA (3xTF32 split) =================
#define IPM 128
#define SH_STRIDE 68     // ≡4 mod 32: A-operand conflict-free
#define SW_STRIDE 72     // ≡8 mod 32: B-operand conflict-free
#define IP_SMEM ((IPM * SH_STRIDE + 64 * SW_STRIDE + 384) * 4)

__device__ __forceinline__ void ip_store(int row, int c, float v0, float v1,
                                         const float* __restrict__ dtb) {
    size_t r = (size_t)row;
    if (c < DI) {
        *reinterpret_cast<float2*>(&g_Z[r * DI + c]) = make_float2(siluf(v0), siluf(v1));
    } else if (c < 2 * DI) {
        *reinterpret_cast<float2*>(&g_X[r * DI + (c - DI)]) = make_float2(siluf(v0), siluf(v1));
    } else if (c < 2 * DI + DS) {
        *reinterpret_cast<float2*>(&g_Bm[r * DS + (c - 2 * DI)]) = make_float2(siluf(v0), siluf(v1));
    } else if (c < 2 * DI + 2 * DS) {
        *reinterpret_cast<float2*>(&g_Cm[r * DS + (c - 2 * DI - DS)]) = make_float2(siluf(v0), siluf(v1));
    } else {
        int hh = c - (2 * DI + 2 * DS);
        *reinterpret_cast<float2*>(&g_dt[r * NH + hh]) =
            make_float2(softplusf(v0 + __ldg(&dtb[hh])), softplusf(v1 + __ldg(&dtb[hh + 1])));
    }
}

__global__ void k_inproj_mma(const float* __restrict__ W,
                             const float* __restrict__ bias,
                             const float* __restrict__ dt_bias,
                             int l) {
    extern __shared__ float smem[];
    float* sH = smem;
    float* sW = sH + IPM * SH_STRIDE;
    float* sBias = sW + 64 * SW_STRIDE;

    const int row0 = blockIdx.x * IPM;
    const int tid = threadIdx.x;
    const int w = tid >> 5, lane = tid & 31;
    const int g = lane >> 2, tq = lane & 3;
    const float* Wl = W + (size_t)l * DM * DPROJ;
    const float* dtb = dt_bias + l * NH;

    for (int idx = tid; idx < IPM * DM; idx += 256) {
        int r = idx >> 6, k = idx & 63;
        sH[r * SH_STRIDE + k] = g_h[(size_t)(row0 + r) * DM + k];
    }
    for (int idx = tid; idx < 384; idx += 256)
        sBias[idx] = (idx < DPROJ) ? bias[l * DPROJ + idx] : 0.f;
    __syncthreads();

    const int rA0 = (w * 16 + g) * SH_STRIDE;
    const int rA1 = (w * 16 + g + 8) * SH_STRIDE;

    for (int chunk = 0; chunk < 6; chunk++) {
        for (int idx = tid; idx < 64 * 64; idx += 256) {
            int k = idx >> 6, n = idx & 63;
            int c = chunk * 64 + n;
            sW[k * SW_STRIDE + n] = (c < DPROJ) ? __ldg(&Wl[(size_t)k * DPROJ + c]) : 0.f;
        }
        __syncthreads();

        float fa[8][4];
#pragma unroll
        for (int nt = 0; nt < 8; nt++)
#pragma unroll
            for (int j = 0; j < 4; j++) fa[nt][j] = 0.f;

#pragma unroll
        for (int k0 = 0; k0 < 64; k0 += 8) {
            unsigned ahi[4], alo[4];
            sp32(sH[rA0 + k0 + tq],     ahi[0], alo[0]);
            sp32(sH[rA1 + k0 + tq],     ahi[1], alo[1]);
            sp32(sH[rA0 + k0 + tq + 4], ahi[2], alo[2]);
            sp32(sH[rA1 + k0 + tq + 4], ahi[3], alo[3]);
#pragma unroll
            for (int nt = 0; nt < 8; nt++) {
                unsigned bhi[2], blo[2];
                sp32(sW[(k0 + tq) * SW_STRIDE + nt * 8 + g],     bhi[0], blo[0]);
                sp32(sW[(k0 + tq + 4) * SW_STRIDE + nt * 8 + g], bhi[1], blo[1]);
                mma_tf32(fa[nt], ahi, bhi);
                mma_tf32(fa[nt], ahi, blo);
                mma_tf32(fa[nt], alo, bhi);
            }
        }
        __syncthreads();

#pragma unroll
        for (int nt = 0; nt < 8; nt++) {
            int cg = chunk * 64 + nt * 8 + 2 * tq;
            if (cg >= DPROJ) continue;
            float b0v = sBias[cg], b1v = sBias[cg + 1];
            int r0 = row0 + w * 16 + g;
            ip_store(r0,     cg, fa[nt][0] + b0v, fa[nt][1] + b1v, dtb);
            ip_store(r0 + 8, cg, fa[nt][2] + b0v, fa[nt][3] + b1v, dtb);
        }
    }
}

// ================= K3: per-chunk summary (R6 scalar, validated) ===========
#define CS_STRIDE 34
__global__ void k_chunk_summary(const float* __restrict__ A_log, int l) {
    const int bx = blockIdx.x;
    const int ch = bx & (NCH - 1);
    const int h  = (bx >> 7) & 3;
    const int b  = bx >> 9;
    const size_t base = (size_t)b * L_ + (size_t)ch * Q;
    __shared__ __align__(8) float sX[Q * CS_STRIDE];
    __shared__ __align__(8) float sB[Q * CS_STRIDE];
    __shared__ float sla[Q], sw_[Q], sdt[Q];
    const int tid = threadIdx.x;               // 256 threads

    for (int idx = tid; idx < Q * 32; idx += 256) {
        int s = idx >> 5, j = idx & 31;
        sX[s * CS_STRIDE + j] = g_X [(base + s) * DI + h * HD + j];
        sB[s * CS_STRIDE + j] = g_Bm[(base + s) * DS + j];
    }
    if (tid < Q) sdt[tid] = g_dt[(base + tid) * NH + h];
    __syncthreads();

    const float A = -expf(A_log[l * NH + h]);
    if (tid < Q) {
        float v = sdt[tid] * A;
#pragma unroll
        for (int o = 1; o < 32; o <<= 1) {
            float u = __shfl_up_sync(0xffffffffu, v, o);
            if ((tid & 31) >= o) v += u;
        }
        sla[tid] = v;
    }
    __syncthreads();
    if (tid >= 32 && tid < 64) sla[tid] += sla[31];
    __syncthreads();
    const float laQ = sla[Q - 1];
    if (tid < Q) {
        g_la[(base + tid) * NH + h] = sla[tid];
        sw_[tid] = sdt[tid] * __expf(laQ - sla[tid]);
    }
    __syncthreads();
    for (int idx = tid; idx < Q * HD; idx += 256) {
        int s = idx >> 5;
        sX[s * CS_STRIDE + (idx & 31)] *= sw_[s];
    }
    __syncthreads();

    const int p0 = (tid >> 4) * 2, n0 = (tid & 15) * 2;
    float a00 = 0.f, a01 = 0.f, a10 = 0.f, a11 = 0.f;
#pragma unroll 8
    for (int s = 0; s < Q; s++) {
        float2 xv = *reinterpret_cast<const float2*>(&sX[s * CS_STRIDE + p0]);
        float2 bv = *reinterpret_cast<const float2*>(&sB[s * CS_STRIDE + n0]);
        a00 += xv.x * bv.x; a01 += xv.x * bv.y;
        a10 += xv.y * bv.x; a11 += xv.y * bv.y;
    }
    float* dst = &g_Sd[(size_t)bx * 1024];
    *reinterpret_cast<float2*>(&dst[p0 * 32 + n0])       = make_float2(a00, a01);
    *reinterpret_cast<float2*>(&dst[(p0 + 1) * 32 + n0]) = make_float2(a10, a11);
    if (tid == 0) g_aQ[bx] = __expf(laQ);
}

// ================= K4a: segment-local scan =================
__global__ void k_scan_seg() {
    const int blk = blockIdx.x;
    const int bh = blk >> 4, seg = blk & (NSEG - 1);
    const int tid = threadIdx.x;       // 1024
    const size_t cbase = (size_t)bh * NCH + seg * CPS;
    float hloc = 0.f;
#pragma unroll
    for (int j = 0; j < CPS; j++) {
        size_t o = (cbase + j) * 1024 + tid;
        g_h0[o] = hloc;
        hloc = __ldg(&g_aQ[cbase + j]) * hloc + g_Sd[o];
    }
    g_segS[(size_t)blk * 1024 + tid] = hloc;
    if (tid == 0) {
        float p = 1.f;
#pragma unroll
        for (int j = 0; j < CPS; j++) p *= g_aQ[cbase + j];
        g_segA[blk] = p;
    }
}

// ================= K4b: top-level segment scan =================
__global__ void k_scan_top() {
    const int bh = blockIdx.x;         // 64 blocks
    const int tid = threadIdx.x;       // 1024
    float carry = 0.f;
#pragma unroll
    for (int seg = 0; seg < NSEG; seg++) {
        size_t o = ((size_t)bh * NSEG + seg) * 1024 + tid;
        g_segIn[o] = carry;
        carry = __ldg(&g_segA[bh * NSEG + seg]) * carry + g_segS[o];
    }
}

// ================= K5: fused chunk-output (4 heads) + out_proj ===========
#define SXO 40    // ≡8 mod 32 (X, B-operand in Y phase)
#define SBC 36    // ≡4 mod 32 (B/C/h0)
#define SGS 68    // ≡4 mod 32 (G)
#define SY2 132   // ≡4 mod 32 (y tile, A-operand in out_proj phase)
// float offsets within dynamic smem
#define F_SX   0
#define F_SY   (F_SX + Q * SXO)                 // 2560
#define F_SLA  (F_SY + Q * SY2)                 // 11008
#define F_SDT  (F_SLA + Q)
#define F_SE   (F_SDT + Q)
#define F_RB   (F_SE + Q + 32)                  // 11232 region base
#define F_SB   (F_RB)
#define F_SC   (F_SB + Q * SBC)
#define F_SH0  (F_SC + Q * SBC)
#define F_SG   (F_SH0 + HD * SBC)
#define F_END  (F_SG + Q * SGS)                 // region = 10112 floats
#define CO2_SMEM (F_END * 4)
// out_proj aliases (over the B/C/h0/G region: needs 128*72+64 = 9280 <= 10112)
#define F_SW2  (F_RB)
#define F_SB2  (F_RB + DI * SW_STRIDE)

__global__ void k_fused_out(const float* __restrict__ Dp,
                            const float* __restrict__ Wo,
                            const float* __restrict__ bo,
                            int l) {
    extern __shared__ float sm[];
    float* sX  = sm + F_SX;
    float* sY  = sm + F_SY;
    float* sla = sm + F_SLA;
    float* sdt = sm + F_SDT;
    float* sE  = sm + F_SE;
    float* sB  = sm + F_SB;
    float* sC  = sm + F_SC;
    float* sh0 = sm + F_SH0;
    float* sG  = sm + F_SG;
    __shared__ float sprefAs[NH];

    const int bx = blockIdx.x;           // b*NCH + ch
    const int ch = bx & (NCH - 1);
    const int b  = bx >> 7;
    const size_t base = (size_t)b * L_ + (size_t)ch * Q;
    const int tid = threadIdx.x;         // 256
    const int w = tid >> 5, lane = tid & 31;
    const int g = lane >> 2, tq = lane & 3;
    const int mrow = (w & 3) * 16;

    if (tid < NH) {
        float p = 1.f;
        int j0 = ch & (CPS - 1);
        size_t cb = (size_t)(b * NH + tid) * NCH + (size_t)(ch & ~(CPS - 1));
        for (int j = 0; j < j0; j++) p *= g_aQ[cb + j];
        sprefAs[tid] = p;
    }
    // B, C shared across heads — load once
    for (int idx = tid; idx < Q * 32; idx += 256) {
        int s = idx >> 5, j = idx & 31;
        sB[s * SBC + j] = g_Bm[(base + s) * DS + j];
        sC[s * SBC + j] = g_Cm[(base + s) * DS + j];
    }
    __syncthreads();

    for (int h = 0; h < NH; h++) {
        const int bhIdx = b * NH + h;
        const size_t bxh = (size_t)bhIdx * NCH + ch;

        for (int idx = tid; idx < Q * 32; idx += 256) {
            int s = idx >> 5, j = idx & 31;
            sX[s * SXO + j] = g_X[(base + s) * DI + h * HD + j];
        }
        if (tid < Q) {
            float la = g_la[(base + tid) * NH + h];
            sla[tid] = la;
            sdt[tid] = g_dt[(base + tid) * NH + h];
            sE[tid] = __expf(la);
        }
        {
            const float pa = sprefAs[h];
            const int seg = ch >> 3;
            const size_t sio = ((size_t)bhIdx * NSEG + seg) * 1024;
            for (int idx = tid; idx < 1024; idx += 256)
                sh0[(idx >> 5) * SBC + (idx & 31)] =
                    g_h0[bxh * 1024 + idx] + pa * g_segIn[sio + idx];
        }
        __syncthreads();

        // ---- Phase 1: G = C . B^T  (M=64 t, N=64 s, K=32 n) ----
        const int shalf = (w >> 2) * 32;
        float ga[4][4];
#pragma unroll
        for (int nt = 0; nt < 4; nt++)
#pragma unroll
            for (int j = 0; j < 4; j++) ga[nt][j] = 0.f;

#pragma unroll
        for (int k0 = 0; k0 < 32; k0 += 8) {
            unsigned ahi[4], alo[4];
            sp32(sC[(mrow + g) * SBC + k0 + tq],         ahi[0], alo[0]);
            sp32(sC[(mrow + g + 8) * SBC + k0 + tq],     ahi[1], alo[1]);
            sp32(sC[(mrow + g) * SBC + k0 + tq + 4],     ahi[2], alo[2]);
            sp32(sC[(mrow + g + 8) * SBC + k0 + tq + 4], ahi[3], alo[3]);
#pragma unroll
            for (int nt = 0; nt < 4; nt++) {
                int sc = shalf + nt * 8 + g;
                unsigned bhi[2], blo[2];
                sp32(sB[sc * SBC + k0 + tq],     bhi[0], blo[0]);
                sp32(sB[sc * SBC + k0 + tq + 4], bhi[1], blo[1]);
                mma_tf32(ga[nt], ahi, bhi);
                mma_tf32(ga[nt], ahi, blo);
                mma_tf32(ga[nt], alo, bhi);
            }
        }

        // ---- Phase 2: mask + exp into sG (own elements; no pre-sync needed) ----
#pragma unroll
        for (int nt = 0; nt < 4; nt++) {
            int s0 = shalf + nt * 8 + 2 * tq;
            int t0 = mrow + g, t1 = mrow + g + 8;
            float la0 = sla[t0], la1 = sla[t1];
            float d0 = sdt[s0], d1 = sdt[s0 + 1];
            float ls0 = sla[s0], ls1 = sla[s0 + 1];
            sG[t0 * SGS + s0]     = (s0 <= t0)     ? ga[nt][0] * d0 * __expf(la0 - ls0) : 0.f;
            sG[t0 * SGS + s0 + 1] = (s0 + 1 <= t0) ? ga[nt][1] * d1 * __expf(la0 - ls1) : 0.f;
            sG[t1 * SGS + s0]     = (s0 <= t1)     ? ga[nt][2] * d0 * __expf(la1 - ls0) : 0.f;
            sG[t1 * SGS + s0 + 1] = (s0 + 1 <= t1) ? ga[nt][3] * d1 * __expf(la1 - ls1) : 0.f;
        }
        __syncthreads();

        // ---- Phase 3: fa = G.X (k=64); fb = C.h0^T (k=32) ----
        const int phalf = (w >> 2) * 16;
        float fa[2][4], fb[2][4];
#pragma unroll
        for (int nt = 0; nt < 2; nt++)
#pragma unroll
            for (int j = 0; j < 4; j++) { fa[nt][j] = 0.f; fb[nt][j] = 0.f; }

#pragma unroll
        for (int k0 = 0; k0 < Q; k0 += 8) {
            unsigned ahi[4], alo[4];
            sp32(sG[(mrow + g) * SGS + k0 + tq],         ahi[0], alo[0]);
            sp32(sG[(mrow + g + 8) * SGS + k0 + tq],     ahi[1], alo[1]);
            sp32(sG[(mrow + g) * SGS + k0 + tq + 4],     ahi[2], alo[2]);
            sp32(sG[(mrow + g + 8) * SGS + k0 + tq + 4], ahi[3], alo[3]);
#pragma unroll
            for (int nt = 0; nt < 2; nt++) {
                int pc = phalf + nt * 8 + g;
                unsigned bhi[2], blo[2];
                sp32(sX[(k0 + tq) * SXO + pc],     bhi[0], blo[0]);
                sp32(sX[(k0 + tq + 4) * SXO + pc], bhi[1], blo[1]);
                mma_tf32(fa[nt], ahi, bhi);
                mma_tf32(fa[nt], ahi, blo);
                mma_tf32(fa[nt], alo, bhi);
            }
        }
#pragma unroll
        for (int k0 = 0; k0 < 32; k0 += 8) {
            unsigned ahi[4], alo[4];
            sp32(sC[(mrow + g) * SBC + k0 + tq],         ahi[0], alo[0]);
            sp32(sC[(mrow + g + 8) * SBC + k0 + tq],     ahi[1], alo[1]);
            sp32(sC[(mrow + g) * SBC + k0 + tq + 4],     ahi[2], alo[2]);
            sp32(sC[(mrow + g + 8) * SBC + k0 + tq + 4], ahi[3], alo[3]);
#pragma unroll
            for (int nt = 0; nt < 2; nt++) {
                int pc = phalf + nt * 8 + g;
                unsigned bhi[2], blo[2];
                sp32(sh0[pc * SBC + k0 + tq],     bhi[0], blo[0]);
                sp32(sh0[pc * SBC + k0 + tq + 4], bhi[1], blo[1]);
                mma_tf32(fb[nt], ahi, bhi);
                mma_tf32(fb[nt], ahi, blo);
                mma_tf32(fb[nt], alo, bhi);
            }
        }

        // ---- Epilogue: y = (fa + E_t*fb + D*x) * z -> sY ----
        const float Dh = Dp[l * NH + h];
        const float E0 = sE[mrow + g], E1 = sE[mrow + g + 8];
#pragma unroll
        for (int nt = 0; nt < 2; nt++) {
            int pc = phalf + nt * 8 + 2 * tq;
            {
                int t = mrow + g;
                size_t o = (base + t) * DI + h * HD + pc;
                float2 z = *reinterpret_cast<const float2*>(&g_Z[o]);
                float2 r;
                r.x = (fa[nt][0] + E0 * fb[nt][0] + Dh * sX[t * SXO + pc]) * z.x;
                r.y = (fa[nt][1] + E0 * fb[nt][1] + Dh * sX[t * SXO + pc + 1]) * z.y;
                *reinterpret_cast<float2*>(&sY[t * SY2 + h * HD + pc]) = r;
            }
            {
                int t = mrow + g + 8;
                size_t o = (base + t) * DI + h * HD + pc;
                float2 z = *reinterpret_cast<const float2*>(&g_Z[o]);
                float2 r;
                r.x = (fa[nt][2] + E1 * fb[nt][2] + Dh * sX[t * SXO + pc]) * z.x;
                r.y = (fa[nt][3] + E1 * fb[nt][3] + Dh * sX[t * SXO + pc + 1]) * z.y;
                *reinterpret_cast<float2*>(&sY[t * SY2 + h * HD + pc]) = r;
            }
        }
        __syncthreads();   // sY complete for this head; safe to reload sX/sh0/sla next head
    }

    // ---- out_proj phase: h += sY @ Wo + bo ----
    float* sW2 = sm + F_SW2;
    float* sB2 = sm + F_SB2;
    {
        const float* Wl = Wo + (size_t)l * DI * DM;
        for (int idx = tid; idx < DI * DM; idx += 256) {
            int k = idx >> 6, n = idx & 63;
            sW2[k * SW_STRIDE + n] = __ldg(&Wl[(size_t)k * DM + n]);
        }
        if (tid < 64) sB2[tid] = bo[l * DM + tid];
    }
    __syncthreads();

    const int nhalf = (w >> 2) * 32;
    const int rA0 = (mrow + g) * SY2;
    const int rA1 = (mrow + g + 8) * SY2;
    float fo[4][4];
#pragma unroll
    for (int nt = 0; nt < 4; nt++)
#pragma unroll
        for (int j = 0; j < 4; j++) fo[nt][j] = 0.f;

#pragma unroll 4
    for (int k0 = 0; k0 < DI; k0 += 8) {
        unsigned ahi[4], alo[4];
        sp32(sY[rA0 + k0 + tq],     ahi[0], alo[0]);
        sp32(sY[rA1 + k0 + tq],     ahi[1], alo[1]);
        sp32(sY[rA0 + k0 + tq + 4], ahi[2], alo[2]);
        sp32(sY[rA1 + k0 + tq + 4], ahi[3], alo[3]);
#pragma unroll
        for (int nt = 0; nt < 4; nt++) {
            unsigned bhi[2], blo[2];
            sp32(sW2[(k0 + tq) * SW_STRIDE + nhalf + nt * 8 + g],     bhi[0], blo[0]);
            sp32(sW2[(k0 + tq + 4) * SW_STRIDE + nhalf + nt * 8 + g], bhi[1], blo[1]);
            mma_tf32(fo[nt], ahi, bhi);
            mma_tf32(fo[nt], ahi, blo);
            mma_tf32(fo[nt], alo, bhi);
        }
    }

#pragma unroll
    for (int nt = 0; nt < 4; nt++) {
        int c = nhalf + nt * 8 + 2 * tq;
        float bc0 = sB2[c], bc1 = sB2[c + 1];
#pragma unroll
        for (int half = 0; half < 2; half++) {
            int t = mrow + g + half * 8;
            size_t o = (base + t) * DM + c;
            float2 hv = *reinterpret_cast<float2*>(&g_h[o]);
            hv.x += fo[nt][half * 2 + 0] + bc0;
            hv.y += fo[nt][half * 2 + 1] + bc1;
            *reinterpret_cast<float2*>(&g_h[o]) = hv;
        }
    }
}

// ================= K7a: pooling partial sums =================
__global__ void k_pool_a() {
    const int b = blockIdx.x >> 4, seg = blockIdx.x & 15;
    const int tid = threadIdx.x;   // 256
    const int d = tid & 63, part = tid >> 6;
    double s = 0.0;
    for (int ll = seg * 512 + part; ll < (seg + 1) * 512; ll += 4)
        s += (double)g_h[((size_t)b * L_ + ll) * DM + d];
    __shared__ double red[4][64];
    red[part][d] = s;
    __syncthreads();
    if (tid < 64)
        g_pool[((size_t)b * 16 + seg) * DM + tid] =
            red[0][tid] + red[1][tid] + red[2][tid] + red[3][tid];
}

// ================= K7b: combine + classifier =================
__global__ void k_pool_cls(const float* __restrict__ cW,
                           const float* __restrict__ cb,
                           float* __restrict__ out) {
    const int b = blockIdx.x;
    const int tid = threadIdx.x;   // 64
    __shared__ double pooled[64];
    double s = 0.0;
    for (int seg = 0; seg < 16; seg++)
        s += g_pool[((size_t)b * 16 + seg) * DM + tid];
    pooled[tid] = s / (double)L_;
    __syncthreads();
    if (tid < OUT_) {
        double acc = (double)cb[tid];
        for (int dd = 0; dd < DM; dd++)
            acc += pooled[dd] * (double)cW[dd * OUT_ + tid];
        out[b * OUT_ + tid] = (float)acc;
    }
}

// ================= launch =================
extern "C" void kernel_launch(void* const* d_in, const int* in_sizes, int n_in,
                              void* d_out, int out_size) {
    const float* x        = (const float*)d_in[0];
    const float* W_in     = (const float*)d_in[1];
    const float* b_in     = (const float*)d_in[2];
    const float* in_proj_W= (const float*)d_in[3];
    const float* in_proj_b= (const float*)d_in[4];
    const float* A_log    = (const float*)d_in[5];
    const float* Dp       = (const float*)d_in[6];
    const float* dt_bias  = (const float*)d_in[7];
    const float* out_proj_W = (const float*)d_in[8];
    const float* out_proj_b = (const float*)d_in[9];
    const float* cls_W    = (const float*)d_in[10];
    const float* cls_b    = (const float*)d_in[11];
    float* out = (float*)d_out;

    cudaFuncSetAttribute(k_inproj_mma, cudaFuncAttributeMaxDynamicSharedMemorySize, IP_SMEM);
    cudaFuncSetAttribute(k_fused_out, cudaFuncAttributeMaxDynamicSharedMemorySize, CO2_SMEM);

    k_linear_in<<<BL / 16, 256>>>(x, W_in, b_in);
    for (int l = 0; l < NL; l++) {
        k_inproj_mma<<<BL / IPM, 256, IP_SMEM>>>(in_proj_W, in_proj_b, dt_bias, l);
        k_chunk_summary<<<B_ * NH * NCH, 256>>>(A_log, l);
        k_scan_seg<<<B_ * NH * NSEG, 1024>>>();
        k_scan_top<<<B_ * NH, 1024>>>();
        k_fused_out<<<B_ * NCH, 256, CO2_SMEM>>>(Dp, out_proj_W, out_proj_b, l);
    }
    k_pool_a<<<B_ * 16, 256>>>();
    k_pool_cls<<<B_, 64>>>(cls_W, cls_b, out);
}

// round 13
// speedup vs baseline: 1.1342x; 1.1342x over previous
#include <cuda_runtime.h>
#include <cuda_bf16.h>
#include <cstdint>

// ---------------- problem constants ----------------
#define B_     16
#define L_     8192
#define IN_    57
#define DM     64
#define DS     32
#define HD     32
#define NH     4
#define DI     128          // EXP*DM
#define DPROJ  324          // 2*DI + 2*DS + NH
#define NL     2
#define OUT_   6
#define Q      64           // chunk length
#define NCH    (L_ / Q)     // 128 chunks
#define NSEG   16           // scan segments
#define CPS    (NCH / NSEG) // 8 chunks per segment
#define BL     (B_ * L_)    // 131072 rows

// ---------------- scratch (device globals; allocation-free) ----------------
__device__ float g_h [BL * DM];
__device__ float g_X [BL * DI];
__device__ float g_Z [BL * DI];
__device__ float g_y [BL * DI];
__device__ float g_Bm[BL * DS];
__device__ float g_Cm[BL * DS];
__device__ float g_dt[BL * NH];
__device__ float g_la[BL * NH];
__device__ float g_Sd[B_ * NH * NCH * HD * DS];    // chunk delta states
__device__ float g_h0[B_ * NH * NCH * HD * DS];    // segment-local entry states
__device__ float g_aQ[B_ * NH * NCH];              // chunk total decay
__device__ float g_segS[B_ * NH * NSEG * HD * DS]; // segment delta states
__device__ float g_segA[B_ * NH * NSEG];           // segment decay product
__device__ float g_segIn[B_ * NH * NSEG * HD * DS];// segment entry states
__device__ double g_pool[B_ * 16 * DM];

// ---------------- helpers ----------------
__device__ __forceinline__ float siluf(float v) { return v / (1.f + __expf(-v)); }
__device__ __forceinline__ float softplusf(float v) { return (v > 20.f) ? v : log1pf(__expf(v)); }

__device__ __forceinline__ unsigned cvt_tf32(float f) {
    unsigned u; asm("cvt.rna.tf32.f32 %0, %1;" : "=r"(u) : "f"(f)); return u;
}
__device__ __forceinline__ void sp32(float v, unsigned& h, unsigned& l) {
    h = cvt_tf32(v);
    l = cvt_tf32(v - __uint_as_float(h));
}
__device__ __forceinline__ void mma_tf32(float* d, const unsigned* a, const unsigned* b) {
    asm volatile("mma.sync.aligned.m16n8k8.row.col.f32.tf32.tf32.f32 "
                 "{%0,%1,%2,%3},{%4,%5,%6,%7},{%8,%9},{%0,%1,%2,%3};"
                 : "+f"(d[0]), "+f"(d[1]), "+f"(d[2]), "+f"(d[3])
                 : "r"(a[0]), "r"(a[1]), "r"(a[2]), "r"(a[3]),
                   "r"(b[0]), "r"(b[1]));
}

// ================= K1: linear_in  h = x @ W_in + b_in =================
__global__ void k_linear_in(const float* __restrict__ x,
                            const float* __restrict__ W,
                            const float* __restrict__ bias) {
    const int row0 = blockIdx.x * 16;
    __shared__ float sx[16][IN_ + 1];
    const int tid = threadIdx.x;
    for (int idx = tid; idx < 16 * IN_; idx += 256) {
        int r = idx / IN_, k = idx % IN_;
        sx[r][k] = x[(size_t)(row0 + r) * IN_ + k];
    }
    __syncthreads();
    const int c = tid & 63, q = tid >> 6;
    float bc = bias[c];
    float acc[4] = {bc, bc, bc, bc};
    for (int k = 0; k < IN_; k++) {
        float wv = __ldg(&W[k * DM + c]);
#pragma unroll
        for (int j = 0; j < 4; j++) acc[j] += sx[q * 4 + j][k] * wv;
    }
#pragma unroll
    for (int j = 0; j < 4; j++)
        g_h[(size_t)(row0 + q * 4 + j) * DM + c] = acc[j];
}

// ================= K2: in_proj via tf32 MMA (double-buffered W) ==========
#define IPM 128
#define SH_STRIDE 68     // ≡4 mod 32: A-operand conflict-free
#define SW_STRIDE 72     // ≡8 mod 32: B-operand conflict-free
#define IP_SMEM ((IPM * SH_STRIDE + 2 * 64 * SW_STRIDE + 384) * 4)

__device__ __forceinline__ void ip_store(int row, int c, float v0, float v1,
                                         const float* __restrict__ dtb) {
    size_t r = (size_t)row;
    if (c < DI) {
        *reinterpret_cast<float2*>(&g_Z[r * DI + c]) = make_float2(siluf(v0), siluf(v1));
    } else if (c < 2 * DI) {
        *reinterpret_cast<float2*>(&g_X[r * DI + (c - DI)]) = make_float2(siluf(v0), siluf(v1));
    } else if (c < 2 * DI + DS) {
        *reinterpret_cast<float2*>(&g_Bm[r * DS + (c - 2 * DI)]) = make_float2(siluf(v0), siluf(v1));
    } else if (c < 2 * DI + 2 * DS) {
        *reinterpret_cast<float2*>(&g_Cm[r * DS + (c - 2 * DI - DS)]) = make_float2(siluf(v0), siluf(v1));
    } else {
        int hh = c - (2 * DI + 2 * DS);
        *reinterpret_cast<float2*>(&g_dt[r * NH + hh]) =
            make_float2(softplusf(v0 + __ldg(&dtb[hh])), softplusf(v1 + __ldg(&dtb[hh + 1])));
    }
}

__global__ void k_inproj_mma(const float* __restrict__ W,
                             const float* __restrict__ bias,
                             const float* __restrict__ dt_bias,
                             int l) {
    extern __shared__ float smem[];
    float* sH = smem;                        // IPM x SH_STRIDE
    float* sW0 = sH + IPM * SH_STRIDE;       // 64 x SW_STRIDE
    float* sW1 = sW0 + 64 * SW_STRIDE;       // 64 x SW_STRIDE
    float* sBias = sW1 + 64 * SW_STRIDE;     // 384

    const int row0 = blockIdx.x * IPM;
    const int tid = threadIdx.x;
    const int w = tid >> 5, lane = tid & 31;
    const int g = lane >> 2, tq = lane & 3;
    const float* Wl = W + (size_t)l * DM * DPROJ;
    const float* dtb = dt_bias + l * NH;

    // W-tile access pattern: each thread owns column n = tid&63, rows 4*i + (tid>>6)
    const int wn = tid & 63, wkhi = tid >> 6;
    float wr[16];

    // prologue: load chunk 0 W, sH (float4), bias
    {
        int c = wn;  // chunk 0
#pragma unroll
        for (int i = 0; i < 16; i++)
            wr[i] = __ldg(&Wl[(size_t)(4 * i + wkhi) * DPROJ + c]);
    }
    for (int idx = tid; idx < IPM * 16; idx += 256) {
        int r = idx >> 4, kq = (idx & 15) * 4;
        float4 v = *reinterpret_cast<const float4*>(&g_h[(size_t)(row0 + r) * DM + kq]);
        *reinterpret_cast<float4*>(&sH[r * SH_STRIDE + kq]) = v;
    }
    for (int idx = tid; idx < 384; idx += 256)
        sBias[idx] = (idx < DPROJ) ? bias[l * DPROJ + idx] : 0.f;
#pragma unroll
    for (int i = 0; i < 16; i++)
        sW0[(4 * i + wkhi) * SW_STRIDE + wn] = wr[i];
    __syncthreads();

    const int rA0 = (w * 16 + g) * SH_STRIDE;
    const int rA1 = (w * 16 + g + 8) * SH_STRIDE;

    for (int chunk = 0; chunk < 6; chunk++) {
        float* sWc = (chunk & 1) ? sW1 : sW0;
        float* sWn = (chunk & 1) ? sW0 : sW1;

        // prefetch next chunk's W into registers (overlaps with MMA below)
        if (chunk < 5) {
            int c = (chunk + 1) * 64 + wn;
            bool ok = c < DPROJ;
#pragma unroll
            for (int i = 0; i < 16; i++)
                wr[i] = ok ? __ldg(&Wl[(size_t)(4 * i + wkhi) * DPROJ + c]) : 0.f;
        }

        float fa[8][4];
#pragma unroll
        for (int nt = 0; nt < 8; nt++)
#pragma unroll
            for (int j = 0; j < 4; j++) fa[nt][j] = 0.f;

#pragma unroll
        for (int k0 = 0; k0 < 64; k0 += 8) {
            unsigned ahi[4], alo[4];
            sp32(sH[rA0 + k0 + tq],     ahi[0], alo[0]);
            sp32(sH[rA1 + k0 + tq],     ahi[1], alo[1]);
            sp32(sH[rA0 + k0 + tq + 4], ahi[2], alo[2]);
            sp32(sH[rA1 + k0 + tq + 4], ahi[3], alo[3]);
#pragma unroll
            for (int nt = 0; nt < 8; nt++) {
                unsigned bhi[2], blo[2];
                sp32(sWc[(k0 + tq) * SW_STRIDE + nt * 8 + g],     bhi[0], blo[0]);
                sp32(sWc[(k0 + tq + 4) * SW_STRIDE + nt * 8 + g], bhi[1], blo[1]);
                mma_tf32(fa[nt], ahi, bhi);
                mma_tf32(fa[nt], ahi, blo);
                mma_tf32(fa[nt], alo, bhi);
            }
        }

        // epilogue store for this chunk (no smem involved)
#pragma unroll
        for (int nt = 0; nt < 8; nt++) {
            int cg = chunk * 64 + nt * 8 + 2 * tq;
            if (cg >= DPROJ) continue;
            float b0v = sBias[cg], b1v = sBias[cg + 1];
            int r0 = row0 + w * 16 + g;
            ip_store(r0,     cg, fa[nt][0] + b0v, fa[nt][1] + b1v, dtb);
            ip_store(r0 + 8, cg, fa[nt][2] + b0v, fa[nt][3] + b1v, dtb);
        }

        // stage next W tile and sync once
        if (chunk < 5) {
#pragma unroll
            for (int i = 0; i < 16; i++)
                sWn[(4 * i + wkhi) * SW_STRIDE + wn] = wr[i];
            __syncthreads();
        }
    }
}

// ================= K3: per-chunk summary (R6 scalar, validated) ===========
#define CS_STRIDE 34
__global__ void k_chunk_summary(const float* __restrict__ A_log, int l) {
    const int bx = blockIdx.x;
    const int ch = bx & (NCH - 1);
    const int h  = (bx >> 7) & 3;
    const int b  = bx >> 9;
    const size_t base = (size_t)b * L_ + (size_t)ch * Q;
    __shared__ __align__(16) float sX[Q * CS_STRIDE];
    __shared__ __align__(16) float sB[Q * CS_STRIDE];
    __shared__ float sla[Q], sw_[Q], sdt[Q];
    const int tid = threadIdx.x;               // 256 threads

    for (int idx = tid; idx < Q * 8; idx += 256) {
        int s = idx >> 3, jq = (idx & 7) * 4;
        float4 xv = *reinterpret_cast<const float4*>(&g_X [(base + s) * DI + h * HD + jq]);
        float4 bv = *reinterpret_cast<const float4*>(&g_Bm[(base + s) * DS + jq]);
        // CS_STRIDE=34 is not multiple of 4 -> scalar stores (row base 34*s may be misaligned for f4)
        sX[s * CS_STRIDE + jq]     = xv.x; sX[s * CS_STRIDE + jq + 1] = xv.y;
        sX[s * CS_STRIDE + jq + 2] = xv.z; sX[s * CS_STRIDE + jq + 3] = xv.w;
        sB[s * CS_STRIDE + jq]     = bv.x; sB[s * CS_STRIDE + jq + 1] = bv.y;
        sB[s * CS_STRIDE + jq + 2] = bv.z; sB[s * CS_STRIDE + jq + 3] = bv.w;
    }
    if (tid < Q) sdt[tid] = g_dt[(base + tid) * NH + h];
    __syncthreads();

    const float A = -expf(A_log[l * NH + h]);
    if (tid < Q) {
        float v = sdt[tid] * A;
#pragma unroll
        for (int o = 1; o < 32; o <<= 1) {
            float u = __shfl_up_sync(0xffffffffu, v, o);
            if ((tid & 31) >= o) v += u;
        }
        sla[tid] = v;
    }
    __syncthreads();
    if (tid >= 32 && tid < 64) sla[tid] += sla[31];
    __syncthreads();
    const float laQ = sla[Q - 1];
    if (tid < Q) {
        g_la[(base + tid) * NH + h] = sla[tid];
        sw_[tid] = sdt[tid] * __expf(laQ - sla[tid]);
    }
    __syncthreads();
    for (int idx = tid; idx < Q * HD; idx += 256) {
        int s = idx >> 5;
        sX[s * CS_STRIDE + (idx & 31)] *= sw_[s];
    }
    __syncthreads();

    const int p0 = (tid >> 4) * 2, n0 = (tid & 15) * 2;
    float a00 = 0.f, a01 = 0.f, a10 = 0.f, a11 = 0.f;
#pragma unroll 8
    for (int s = 0; s < Q; s++) {
        float2 xv = *reinterpret_cast<const float2*>(&sX[s * CS_STRIDE + p0]);
        float2 bv = *reinterpret_cast<const float2*>(&sB[s * CS_STRIDE + n0]);
        a00 += xv.x * bv.x; a01 += xv.x * bv.y;
        a10 += xv.y * bv.x; a11 += xv.y * bv.y;
    }
    float* dst = &g_Sd[(size_t)bx * 1024];
    *reinterpret_cast<float2*>(&dst[p0 * 32 + n0])       = make_float2(a00, a01);
    *reinterpret_cast<float2*>(&dst[(p0 + 1) * 32 + n0]) = make_float2(a10, a11);
    if (tid == 0) g_aQ[bx] = __expf(laQ);
}

// ================= K4a: segment-local scan =================
__global__ void k_scan_seg() {
    const int blk = blockIdx.x;
    const int bh = blk >> 4, seg = blk & (NSEG - 1);
    const int tid = threadIdx.x;       // 1024
    const size_t cbase = (size_t)bh * NCH + seg * CPS;
    float hloc = 0.f;
#pragma unroll
    for (int j = 0; j < CPS; j++) {
        size_t o = (cbase + j) * 1024 + tid;
        g_h0[o] = hloc;
        hloc = __ldg(&g_aQ[cbase + j]) * hloc + g_Sd[o];
    }
    g_segS[(size_t)blk * 1024 + tid] = hloc;
    if (tid == 0) {
        float p = 1.f;
#pragma unroll
        for (int j = 0; j < CPS; j++) p *= g_aQ[cbase + j];
        g_segA[blk] = p;
    }
}

// ================= K4b: top-level segment scan =================
__global__ void k_scan_top() {
    const int bh = blockIdx.x;         // 64 blocks
    const int tid = threadIdx.x;       // 1024
    float carry = 0.f;
#pragma unroll
    for (int seg = 0; seg < NSEG; seg++) {
        size_t o = ((size_t)bh * NSEG + seg) * 1024 + tid;
        g_segIn[o] = carry;
        carry = __ldg(&g_segA[bh * NSEG + seg]) * carry + g_segS[o];
    }
}

// ================= K5: chunk output via tf32 MMA (fb epilogue) ===========
#define SXO 40   // ≡8 mod 32
#define SBC 36   // ≡4 mod 32
#define SGS 68   // ≡4 mod 32
#define CO_SMEM ((Q*SXO + Q*SBC + Q*SBC + HD*SBC + Q*SGS + 3*Q) * 4)

__global__ void k_chunk_output_mma(const float* __restrict__ Dp, int l) {
    extern __shared__ float sm[];
    float* sX  = sm;                     // [64][SXO]
    float* sB  = sX + Q * SXO;           // [64][SBC]
    float* sC  = sB + Q * SBC;           // [64][SBC]  (stays pristine)
    float* sh0 = sC + Q * SBC;           // [32][SBC]
    float* sG  = sh0 + HD * SBC;         // [64][SGS]
    float* sla = sG + Q * SGS;           // [64]
    float* sdt = sla + Q;                // [64]
    float* sE  = sdt + Q;                // [64] exp(la_t)
    __shared__ float sprefA;

    const int bx = blockIdx.x;
    const int ch = bx & (NCH - 1);
    const int h  = (bx >> 7) & 3;
    const int b  = bx >> 9;
    const int bhIdx = b * NH + h;
    const size_t base = (size_t)b * L_ + (size_t)ch * Q;
    const int tid = threadIdx.x;         // 256
    const int w = tid >> 5, lane = tid & 31;
    const int g = lane >> 2, tq = lane & 3;
    const int mrow = (w & 3) * 16;       // M stripe (t rows)

    if (tid == 0) {
        float p = 1.f;
        int j0 = ch & (CPS - 1);
        size_t cb = (size_t)bhIdx * NCH + (size_t)(ch & ~(CPS - 1));
        for (int j = 0; j < j0; j++) p *= g_aQ[cb + j];
        sprefA = p;
    }
    for (int idx = tid; idx < Q * 8; idx += 256) {
        int s = idx >> 3, jq = (idx & 7) * 4;
        float4 xv = *reinterpret_cast<const float4*>(&g_X [(base + s) * DI + h * HD + jq]);
        float4 bv = *reinterpret_cast<const float4*>(&g_Bm[(base + s) * DS + jq]);
        float4 cv = *reinterpret_cast<const float4*>(&g_Cm[(base + s) * DS + jq]);
        *reinterpret_cast<float4*>(&sX[s * SXO + jq]) = xv;
        *reinterpret_cast<float4*>(&sB[s * SBC + jq]) = bv;
        *reinterpret_cast<float4*>(&sC[s * SBC + jq]) = cv;
    }
    if (tid < Q) {
        float la = g_la[(base + tid) * NH + h];
        sla[tid] = la;
        sdt[tid] = g_dt[(base + tid) * NH + h];
        sE[tid] = __expf(la);
    }
    // combined entry state into sh0[p][n]  (one float4 per thread: 1024 floats)
    {
        // sprefA written by tid 0 above — need it visible; compute locally instead
        float p = 1.f;
        int j0 = ch & (CPS - 1);
        size_t cb = (size_t)bhIdx * NCH + (size_t)(ch & ~(CPS - 1));
        for (int j = 0; j < j0; j++) p *= __ldg(&g_aQ[cb + j]);
        const int idx4 = tid * 4;
        const int seg = ch >> 3;
        const size_t sio = ((size_t)bhIdx * NSEG + seg) * 1024;
        float4 a = *reinterpret_cast<const float4*>(&g_h0[(size_t)bx * 1024 + idx4]);
        float4 si = *reinterpret_cast<const float4*>(&g_segIn[sio + idx4]);
        int pr = idx4 >> 5, j = idx4 & 31;
        float4 r;
        r.x = a.x + p * si.x; r.y = a.y + p * si.y;
        r.z = a.z + p * si.z; r.w = a.w + p * si.w;
        *reinterpret_cast<float4*>(&sh0[pr * SBC + j]) = r;
    }
    __syncthreads();

    // ---- Phase 1: G = C . B^T  (M=64 t, N=64 s, K=32 n) ----
    const int shalf = (w >> 2) * 32;
    float ga[4][4];
#pragma unroll
    for (int nt = 0; nt < 4; nt++)
#pragma unroll
        for (int j = 0; j < 4; j++) ga[nt][j] = 0.f;

#pragma unroll
    for (int k0 = 0; k0 < 32; k0 += 8) {
        unsigned ahi[4], alo[4];
        sp32(sC[(mrow + g) * SBC + k0 + tq],         ahi[0], alo[0]);
        sp32(sC[(mrow + g + 8) * SBC + k0 + tq],     ahi[1], alo[1]);
        sp32(sC[(mrow + g) * SBC + k0 + tq + 4],     ahi[2], alo[2]);
        sp32(sC[(mrow + g + 8) * SBC + k0 + tq + 4], ahi[3], alo[3]);
#pragma unroll
        for (int nt = 0; nt < 4; nt++) {
            int sc = shalf + nt * 8 + g;
            unsigned bhi[2], blo[2];
            sp32(sB[sc * SBC + k0 + tq],     bhi[0], blo[0]);
            sp32(sB[sc * SBC + k0 + tq + 4], bhi[1], blo[1]);
            mma_tf32(ga[nt], ahi, bhi);
            mma_tf32(ga[nt], ahi, blo);
            mma_tf32(ga[nt], alo, bhi);
        }
    }

    // ---- Phase 2: mask+exp into sG (own elements; distinct region) ----
#pragma unroll
    for (int nt = 0; nt < 4; nt++) {
        int s0 = shalf + nt * 8 + 2 * tq;
        int t0 = mrow + g, t1 = mrow + g + 8;
        float la0 = sla[t0], la1 = sla[t1];
        float d0 = sdt[s0], d1 = sdt[s0 + 1];
        float ls0 = sla[s0], ls1 = sla[s0 + 1];
        sG[t0 * SGS + s0]     = (s0 <= t0)     ? ga[nt][0] * d0 * __expf(la0 - ls0) : 0.f;
        sG[t0 * SGS + s0 + 1] = (s0 + 1 <= t0) ? ga[nt][1] * d1 * __expf(la0 - ls1) : 0.f;
        sG[t1 * SGS + s0]     = (s0 <= t1)     ? ga[nt][2] * d0 * __expf(la1 - ls0) : 0.f;
        sG[t1 * SGS + s0 + 1] = (s0 + 1 <= t1) ? ga[nt][3] * d1 * __expf(la1 - ls1) : 0.f;
    }
    __syncthreads();

    // ---- Phase 3: fa = G.X (k=64); fb = C.h0^T (k=32) ----
    const int phalf = (w >> 2) * 16;
    float fa[2][4], fb[2][4];
#pragma unroll
    for (int nt = 0; nt < 2; nt++)
#pragma unroll
        for (int j = 0; j < 4; j++) { fa[nt][j] = 0.f; fb[nt][j] = 0.f; }

#pragma unroll
    for (int k0 = 0; k0 < Q; k0 += 8) {
        unsigned ahi[4], alo[4];
        sp32(sG[(mrow + g) * SGS + k0 + tq],         ahi[0], alo[0]);
        sp32(sG[(mrow + g + 8) * SGS + k0 + tq],     ahi[1], alo[1]);
        sp32(sG[(mrow + g) * SGS + k0 + tq + 4],     ahi[2], alo[2]);
        sp32(sG[(mrow + g + 8) * SGS + k0 + tq + 4], ahi[3], alo[3]);
#pragma unroll
        for (int nt = 0; nt < 2; nt++) {
            int pc = phalf + nt * 8 + g;
            unsigned bhi[2], blo[2];
            sp32(sX[(k0 + tq) * SXO + pc],     bhi[0], blo[0]);
            sp32(sX[(k0 + tq + 4) * SXO + pc], bhi[1], blo[1]);
            mma_tf32(fa[nt], ahi, bhi);
            mma_tf32(fa[nt], ahi, blo);
            mma_tf32(fa[nt], alo, bhi);
        }
    }
#pragma unroll
    for (int k0 = 0; k0 < 32; k0 += 8) {
        unsigned ahi[4], alo[4];
        sp32(sC[(mrow + g) * SBC + k0 + tq],         ahi[0], alo[0]);
        sp32(sC[(mrow + g + 8) * SBC + k0 + tq],     ahi[1], alo[1]);
        sp32(sC[(mrow + g) * SBC + k0 + tq + 4],     ahi[2], alo[2]);
        sp32(sC[(mrow + g + 8) * SBC + k0 + tq + 4], ahi[3], alo[3]);
#pragma unroll
        for (int nt = 0; nt < 2; nt++) {
            int pc = phalf + nt * 8 + g;
            unsigned bhi[2], blo[2];
            sp32(sh0[pc * SBC + k0 + tq],     bhi[0], blo[0]);
            sp32(sh0[pc * SBC + k0 + tq + 4], bhi[1], blo[1]);
            mma_tf32(fb[nt], ahi, bhi);
            mma_tf32(fb[nt], ahi, blo);
            mma_tf32(fb[nt], alo, bhi);
        }
    }

    // ---- Epilogue: y = (fa + E_t*fb + D*x) * z ----
    const float Dh = Dp[l * NH + h];
    const float E0 = sE[mrow + g], E1 = sE[mrow + g + 8];
#pragma unroll
    for (int nt = 0; nt < 2; nt++) {
        int pc = phalf + nt * 8 + 2 * tq;
        {
            int t = mrow + g;
            size_t o = (base + t) * DI + h * HD + pc;
            float2 z = *reinterpret_cast<const float2*>(&g_Z[o]);
            float2 r;
            r.x = (fa[nt][0] + E0 * fb[nt][0] + Dh * sX[t * SXO + pc]) * z.x;
            r.y = (fa[nt][1] + E0 * fb[nt][1] + Dh * sX[t * SXO + pc + 1]) * z.y;
            *reinterpret_cast<float2*>(&g_y[o]) = r;
        }
        {
            int t = mrow + g + 8;
            size_t o = (base + t) * DI + h * HD + pc;
            float2 z = *reinterpret_cast<const float2*>(&g_Z[o]);
            float2 r;
            r.x = (fa[nt][2] + E1 * fb[nt][2] + Dh * sX[t * SXO + pc]) * z.x;
            r.y = (fa[nt][3] + E1 * fb[nt][3] + Dh * sX[t * SXO + pc + 1]) * z.y;
            *reinterpret_cast<float2*>(&g_y[o]) = r;
        }
    }
}

// ================= K6: out_proj via tf32 MMA + residual =================
#define OPM 128
#define SY_STRIDE 132    // ≡4 mod 32
#define OP_SMEM ((OPM * SY_STRIDE + DI * SW_STRIDE + 64) * 4)
__global__ void k_outproj_mma(const float* __restrict__ Wo,
                              const float* __restrict__ bo,
                              int l) {
    extern __shared__ float smem[];
    float* sY = smem;
    float* sW2 = sY + OPM * SY_STRIDE;
    float* sB2 = sW2 + DI * SW_STRIDE;

    const int row0 = blockIdx.x * OPM;
    const int tid = threadIdx.x;
    const int w = tid >> 5, lane = tid & 31;
    const int g = lane >> 2, tq = lane & 3;
    const float* Wl = Wo + (size_t)l * DI * DM;

    for (int idx = tid; idx < OPM * 32; idx += 256) {
        int r = idx >> 5, kq = (idx & 31) * 4;
        float4 v = *reinterpret_cast<const float4*>(&g_y[(size_t)(row0 + r) * DI + kq]);
        *reinterpret_cast<float4*>(&sY[r * SY_STRIDE + kq]) = v;
    }
    for (int idx = tid; idx < DI * 16; idx += 256) {
        int k = idx >> 4, nq = (idx & 15) * 4;
        float4 v = *reinterpret_cast<const float4*>(&Wl[(size_t)k * DM + nq]);
        *reinterpret_cast<float4*>(&sW2[k * SW_STRIDE + nq]) = v;
    }
    if (tid < 64) sB2[tid] = bo[l * DM + tid];
    __syncthreads();

    const int rA0 = (w * 16 + g) * SY_STRIDE;
    const int rA1 = (w * 16 + g + 8) * SY_STRIDE;

    float fa[8][4];
#pragma unroll
    for (int nt = 0; nt < 8; nt++)
#pragma unroll
        for (int j = 0; j < 4; j++) fa[nt][j] = 0.f;

#pragma unroll 4
    for (int k0 = 0; k0 < DI; k0 += 8) {
        unsigned ahi[4], alo[4];
        sp32(sY[rA0 + k0 + tq],     ahi[0], alo[0]);
        sp32(sY[rA1 + k0 + tq],     ahi[1], alo[1]);
        sp32(sY[rA0 + k0 + tq + 4], ahi[2], alo[2]);
        sp32(sY[rA1 + k0 + tq + 4], ahi[3], alo[3]);
#pragma unroll
        for (int nt = 0; nt < 8; nt++) {
            unsigned bhi[2], blo[2];
            sp32(sW2[(k0 + tq) * SW_STRIDE + nt * 8 + g],     bhi[0], blo[0]);
            sp32(sW2[(k0 + tq + 4) * SW_STRIDE + nt * 8 + g], bhi[1], blo[1]);
            mma_tf32(fa[nt], ahi, bhi);
            mma_tf32(fa[nt], ahi, blo);
            mma_tf32(fa[nt], alo, bhi);
        }
    }

#pragma unroll
    for (int nt = 0; nt < 8; nt++) {
        int c = nt * 8 + 2 * tq;
        float bc0 = sB2[c], bc1 = sB2[c + 1];
        int r0 = row0 + w * 16 + g;
#pragma unroll
        for (int half = 0; half < 2; half++) {
            int r = r0 + half * 8;
            size_t o = (size_t)r * DM + c;
            float2 hv = *reinterpret_cast<float2*>(&g_h[o]);
            hv.x += fa[nt][half * 2 + 0] + bc0;
            hv.y += fa[nt][half * 2 + 1] + bc1;
            *reinterpret_cast<float2*>(&g_h[o]) = hv;
        }
    }
}

// ================= K7a: pooling partial sums =================
__global__ void k_pool_a() {
    const int b = blockIdx.x >> 4, seg = blockIdx.x & 15;
    const int tid = threadIdx.x;   // 256
    const int d = tid & 63, part = tid >> 6;
    double s = 0.0;
    for (int ll = seg * 512 + part; ll < (seg + 1) * 512; ll += 4)
        s += (double)g_h[((size_t)b * L_ + ll) * DM + d];
    __shared__ double red[4][64];
    red[part][d] = s;
    __syncthreads();
    if (tid < 64)
        g_pool[((size_t)b * 16 + seg) * DM + tid] =
            red[0][tid] + red[1][tid] + red[2][tid] + red[3][tid];
}

// ================= K7b: combine + classifier =================
__global__ void k_pool_cls(const float* __restrict__ cW,
                           const float* __restrict__ cb,
                           float* __restrict__ out) {
    const int b = blockIdx.x;
    const int tid = threadIdx.x;   // 64
    __shared__ double pooled[64];
    double s = 0.0;
    for (int seg = 0; seg < 16; seg++)
        s += g_pool[((size_t)b * 16 + seg) * DM + tid];
    pooled[tid] = s / (double)L_;
    __syncthreads();
    if (tid < OUT_) {
        double acc = (double)cb[tid];
        for (int dd = 0; dd < DM; dd++)
            acc += pooled[dd] * (double)cW[dd * OUT_ + tid];
        out[b * OUT_ + tid] = (float)acc;
    }
}

// ================= launch =================
extern "C" void kernel_launch(void* const* d_in, const int* in_sizes, int n_in,
                              void* d_out, int out_size) {
    const float* x        = (const float*)d_in[0];
    const float* W_in     = (const float*)d_in[1];
    const float* b_in     = (const float*)d_in[2];
    const float* in_proj_W= (const float*)d_in[3];
    const float* in_proj_b= (const float*)d_in[4];
    const float* A_log    = (const float*)d_in[5];
    const float* Dp       = (const float*)d_in[6];
    const float* dt_bias  = (const float*)d_in[7];
    const float* out_proj_W = (const float*)d_in[8];
    const float* out_proj_b = (const float*)d_in[9];
    const float* cls_W    = (const float*)d_in[10];
    const float* cls_b    = (const float*)d_in[11];
    float* out = (float*)d_out;

    cudaFuncSetAttribute(k_inproj_mma, cudaFuncAttributeMaxDynamicSharedMemorySize, IP_SMEM);
    cudaFuncSetAttribute(k_outproj_mma, cudaFuncAttributeMaxDynamicSharedMemorySize, OP_SMEM);
    cudaFuncSetAttribute(k_chunk_output_mma, cudaFuncAttributeMaxDynamicSharedMemorySize, CO_SMEM);

    k_linear_in<<<BL / 16, 256>>>(x, W_in, b_in);
    for (int l = 0; l < NL; l++) {
        k_inproj_mma<<<BL / IPM, 256, IP_SMEM>>>(in_proj_W, in_proj_b, dt_bias, l);
        k_chunk_summary<<<B_ * NH * NCH, 256>>>(A_log, l);
        k_scan_seg<<<B_ * NH * NSEG, 1024>>>();
        k_scan_top<<<B_ * NH, 1024>>>();
        k_chunk_output_mma<<<B_ * NH * NCH, 256, CO_SMEM>>>(Dp, l);
        k_outproj_mma<<<BL / OPM, 256, OP_SMEM>>>(out_proj_W, out_proj_b, l);
    }
    k_pool_a<<<B_ * 16, 256>>>();
    k_pool_cls<<<B_, 64>>>(cls_W, cls_b, out);
}

// round 14
// speedup vs baseline: 1.1407x; 1.0057x over previous
#include <cuda_runtime.h>
#include <cuda_bf16.h>
#include <cstdint>

// ---------------- problem constants ----------------
#define B_     16
#define L_     8192
#define IN_    57
#define DM     64
#define DS     32
#define HD     32
#define NH     4
#define DI     128          // EXP*DM
#define DPROJ  324          // 2*DI + 2*DS + NH
#define NL     2
#define OUT_   6
#define Q      64           // chunk length
#define NCH    (L_ / Q)     // 128 chunks
#define NSEG   16           // scan segments
#define CPS    (NCH / NSEG) // 8 chunks per segment
#define BL     (B_ * L_)    // 131072 rows

// ---------------- scratch (device globals; allocation-free) ----------------
__device__ float g_h [BL * DM];
__device__ float g_X [BL * DI];
__device__ float g_Z [BL * DI];
__device__ float g_y [BL * DI];
__device__ float g_Bm[BL * DS];
__device__ float g_Cm[BL * DS];
__device__ float g_dt[BL * NH];
__device__ float g_la[BL * NH];
__device__ float g_Sd[B_ * NH * NCH * HD * DS];    // chunk delta states
__device__ float g_h0[B_ * NH * NCH * HD * DS];    // segment-local entry states
__device__ float g_aQ[B_ * NH * NCH];              // chunk total decay
__device__ float g_segS[B_ * NH * NSEG * HD * DS]; // segment delta states
__device__ float g_segA[B_ * NH * NSEG];           // segment decay product
__device__ float g_segIn[B_ * NH * NSEG * HD * DS];// segment entry states
__device__ double g_pool[B_ * 16 * DM];

// ---------------- helpers ----------------
__device__ __forceinline__ float siluf(float v) { return v / (1.f + __expf(-v)); }
__device__ __forceinline__ float softplusf(float v) { return (v > 20.f) ? v : log1pf(__expf(v)); }

__device__ __forceinline__ unsigned cvt_tf32(float f) {
    unsigned u; asm("cvt.rna.tf32.f32 %0, %1;" : "=r"(u) : "f"(f)); return u;
}
__device__ __forceinline__ void sp32(float v, unsigned& h, unsigned& l) {
    h = cvt_tf32(v);
    l = cvt_tf32(v - __uint_as_float(h));
}
__device__ __forceinline__ void mma_tf32(float* d, const unsigned* a, const unsigned* b) {
    asm volatile("mma.sync.aligned.m16n8k8.row.col.f32.tf32.tf32.f32 "
                 "{%0,%1,%2,%3},{%4,%5,%6,%7},{%8,%9},{%0,%1,%2,%3};"
                 : "+f"(d[0]), "+f"(d[1]), "+f"(d[2]), "+f"(d[3])
                 : "r"(a[0]), "r"(a[1]), "r"(a[2]), "r"(a[3]),
                   "r"(b[0]), "r"(b[1]));
}

// ================= K1: linear_in  h = x @ W_in + b_in =================
__global__ void k_linear_in(const float* __restrict__ x,
                            const float* __restrict__ W,
                            const float* __restrict__ bias) {
    const int row0 = blockIdx.x * 16;
    __shared__ float sx[16][IN_ + 1];
    const int tid = threadIdx.x;
    for (int idx = tid; idx < 16 * IN_; idx += 256) {
        int r = idx / IN_, k = idx % IN_;
        sx[r][k] = x[(size_t)(row0 + r) * IN_ + k];
    }
    __syncthreads();
    const int c = tid & 63, q = tid >> 6;
    float bc = bias[c];
    float acc[4] = {bc, bc, bc, bc};
    for (int k = 0; k < IN_; k++) {
        float wv = __ldg(&W[k * DM + c]);
#pragma unroll
        for (int j = 0; j < 4; j++) acc[j] += sx[q * 4 + j][k] * wv;
    }
#pragma unroll
    for (int j = 0; j < 4; j++)
        g_h[(size_t)(row0 + q * 4 + j) * DM + c] = acc[j];
}

// ================= K2: in_proj via tf32 MMA (double-buffered W) ==========
#define IPM 128
#define SH_STRIDE 68     // ≡4 mod 32: A-operand conflict-free
#define SW_STRIDE 72     // ≡8 mod 32: B-operand conflict-free
#define IP_SMEM ((IPM * SH_STRIDE + 2 * 64 * SW_STRIDE + 384) * 4)

__device__ __forceinline__ void ip_store(int row, int c, float v0, float v1,
                                         const float* __restrict__ dtb) {
    size_t r = (size_t)row;
    if (c < DI) {
        *reinterpret_cast<float2*>(&g_Z[r * DI + c]) = make_float2(siluf(v0), siluf(v1));
    } else if (c < 2 * DI) {
        *reinterpret_cast<float2*>(&g_X[r * DI + (c - DI)]) = make_float2(siluf(v0), siluf(v1));
    } else if (c < 2 * DI + DS) {
        *reinterpret_cast<float2*>(&g_Bm[r * DS + (c - 2 * DI)]) = make_float2(siluf(v0), siluf(v1));
    } else if (c < 2 * DI + 2 * DS) {
        *reinterpret_cast<float2*>(&g_Cm[r * DS + (c - 2 * DI - DS)]) = make_float2(siluf(v0), siluf(v1));
    } else {
        int hh = c - (2 * DI + 2 * DS);
        *reinterpret_cast<float2*>(&g_dt[r * NH + hh]) =
            make_float2(softplusf(v0 + __ldg(&dtb[hh])), softplusf(v1 + __ldg(&dtb[hh + 1])));
    }
}

__global__ void k_inproj_mma(const float* __restrict__ W,
                             const float* __restrict__ bias,
                             const float* __restrict__ dt_bias,
                             int l) {
    extern __shared__ float smem[];
    float* sH = smem;                        // IPM x SH_STRIDE
    float* sW0 = sH + IPM * SH_STRIDE;       // 64 x SW_STRIDE
    float* sW1 = sW0 + 64 * SW_STRIDE;       // 64 x SW_STRIDE
    float* sBias = sW1 + 64 * SW_STRIDE;     // 384

    const int row0 = blockIdx.x * IPM;
    const int tid = threadIdx.x;
    const int w = tid >> 5, lane = tid & 31;
    const int g = lane >> 2, tq = lane & 3;
    const float* Wl = W + (size_t)l * DM * DPROJ;
    const float* dtb = dt_bias + l * NH;

    const int wn = tid & 63, wkhi = tid >> 6;
    float wr[16];

    {
        int c = wn;  // chunk 0
#pragma unroll
        for (int i = 0; i < 16; i++)
            wr[i] = __ldg(&Wl[(size_t)(4 * i + wkhi) * DPROJ + c]);
    }
    for (int idx = tid; idx < IPM * 16; idx += 256) {
        int r = idx >> 4, kq = (idx & 15) * 4;
        float4 v = *reinterpret_cast<const float4*>(&g_h[(size_t)(row0 + r) * DM + kq]);
        *reinterpret_cast<float4*>(&sH[r * SH_STRIDE + kq]) = v;
    }
    for (int idx = tid; idx < 384; idx += 256)
        sBias[idx] = (idx < DPROJ) ? bias[l * DPROJ + idx] : 0.f;
#pragma unroll
    for (int i = 0; i < 16; i++)
        sW0[(4 * i + wkhi) * SW_STRIDE + wn] = wr[i];
    __syncthreads();

    const int rA0 = (w * 16 + g) * SH_STRIDE;
    const int rA1 = (w * 16 + g + 8) * SH_STRIDE;

    for (int chunk = 0; chunk < 6; chunk++) {
        float* sWc = (chunk & 1) ? sW1 : sW0;
        float* sWn = (chunk & 1) ? sW0 : sW1;

        if (chunk < 5) {
            int c = (chunk + 1) * 64 + wn;
            bool ok = c < DPROJ;
#pragma unroll
            for (int i = 0; i < 16; i++)
                wr[i] = ok ? __ldg(&Wl[(size_t)(4 * i + wkhi) * DPROJ + c]) : 0.f;
        }

        float fa[8][4];
#pragma unroll
        for (int nt = 0; nt < 8; nt++)
#pragma unroll
            for (int j = 0; j < 4; j++) fa[nt][j] = 0.f;

#pragma unroll
        for (int k0 = 0; k0 < 64; k0 += 8) {
            unsigned ahi[4], alo[4];
            sp32(sH[rA0 + k0 + tq],     ahi[0], alo[0]);
            sp32(sH[rA1 + k0 + tq],     ahi[1], alo[1]);
            sp32(sH[rA0 + k0 + tq + 4], ahi[2], alo[2]);
            sp32(sH[rA1 + k0 + tq + 4], ahi[3], alo[3]);
#pragma unroll
            for (int nt = 0; nt < 8; nt++) {
                unsigned bhi[2], blo[2];
                sp32(sWc[(k0 + tq) * SW_STRIDE + nt * 8 + g],     bhi[0], blo[0]);
                sp32(sWc[(k0 + tq + 4) * SW_STRIDE + nt * 8 + g], bhi[1], blo[1]);
                mma_tf32(fa[nt], ahi, bhi);
                mma_tf32(fa[nt], ahi, blo);
                mma_tf32(fa[nt], alo, bhi);
            }
        }

#pragma unroll
        for (int nt = 0; nt < 8; nt++) {
            int cg = chunk * 64 + nt * 8 + 2 * tq;
            if (cg >= DPROJ) continue;
            float b0v = sBias[cg], b1v = sBias[cg + 1];
            int r0 = row0 + w * 16 + g;
            ip_store(r0,     cg, fa[nt][0] + b0v, fa[nt][1] + b1v, dtb);
            ip_store(r0 + 8, cg, fa[nt][2] + b0v, fa[nt][3] + b1v, dtb);
        }

        if (chunk < 5) {
#pragma unroll
            for (int i = 0; i < 16; i++)
                sWn[(4 * i + wkhi) * SW_STRIDE + wn] = wr[i];
            __syncthreads();
        }
    }
}

// ================= K3: per-chunk summary (4 heads per block) =============
#define CS_STRIDE 34
__global__ void k_chunk_summary(const float* __restrict__ A_log, int l) {
    const int bx = blockIdx.x;           // b*NCH + ch (2048 blocks)
    const int ch = bx & (NCH - 1);
    const int b  = bx >> 7;
    const size_t base = (size_t)b * L_ + (size_t)ch * Q;
    __shared__ __align__(16) float sX[Q * CS_STRIDE];
    __shared__ __align__(16) float sB[Q * CS_STRIDE];
    __shared__ float sla[Q], sw_[Q], sdt[Q];
    const int tid = threadIdx.x;               // 256 threads

    // B tile: head-invariant, load once
    for (int idx = tid; idx < Q * 8; idx += 256) {
        int s = idx >> 3, jq = (idx & 7) * 4;
        float4 bv = *reinterpret_cast<const float4*>(&g_Bm[(base + s) * DS + jq]);
        sB[s * CS_STRIDE + jq]     = bv.x; sB[s * CS_STRIDE + jq + 1] = bv.y;
        sB[s * CS_STRIDE + jq + 2] = bv.z; sB[s * CS_STRIDE + jq + 3] = bv.w;
    }

    for (int h = 0; h < NH; h++) {
        const size_t bhch = ((size_t)(b * NH + h)) * NCH + ch;

        for (int idx = tid; idx < Q * 8; idx += 256) {
            int s = idx >> 3, jq = (idx & 7) * 4;
            float4 xv = *reinterpret_cast<const float4*>(&g_X[(base + s) * DI + h * HD + jq]);
            sX[s * CS_STRIDE + jq]     = xv.x; sX[s * CS_STRIDE + jq + 1] = xv.y;
            sX[s * CS_STRIDE + jq + 2] = xv.z; sX[s * CS_STRIDE + jq + 3] = xv.w;
        }
        if (tid < Q) sdt[tid] = g_dt[(base + tid) * NH + h];
        __syncthreads();

        const float A = -expf(A_log[l * NH + h]);
        if (tid < Q) {
            float v = sdt[tid] * A;
#pragma unroll
            for (int o = 1; o < 32; o <<= 1) {
                float u = __shfl_up_sync(0xffffffffu, v, o);
                if ((tid & 31) >= o) v += u;
            }
            sla[tid] = v;
        }
        __syncthreads();
        if (tid >= 32 && tid < 64) sla[tid] += sla[31];
        __syncthreads();
        const float laQ = sla[Q - 1];
        if (tid < Q) {
            g_la[(base + tid) * NH + h] = sla[tid];
            sw_[tid] = sdt[tid] * __expf(laQ - sla[tid]);
        }
        __syncthreads();
        for (int idx = tid; idx < Q * HD; idx += 256) {
            int s = idx >> 5;
            sX[s * CS_STRIDE + (idx & 31)] *= sw_[s];
        }
        __syncthreads();

        const int p0 = (tid >> 4) * 2, n0 = (tid & 15) * 2;
        float a00 = 0.f, a01 = 0.f, a10 = 0.f, a11 = 0.f;
#pragma unroll 8
        for (int s = 0; s < Q; s++) {
            float2 xv = *reinterpret_cast<const float2*>(&sX[s * CS_STRIDE + p0]);
            float2 bv = *reinterpret_cast<const float2*>(&sB[s * CS_STRIDE + n0]);
            a00 += xv.x * bv.x; a01 += xv.x * bv.y;
            a10 += xv.y * bv.x; a11 += xv.y * bv.y;
        }
        float* dst = &g_Sd[bhch * 1024];
        *reinterpret_cast<float2*>(&dst[p0 * 32 + n0])       = make_float2(a00, a01);
        *reinterpret_cast<float2*>(&dst[(p0 + 1) * 32 + n0]) = make_float2(a10, a11);
        if (tid == 0) g_aQ[bhch] = __expf(laQ);
        __syncthreads();   // sX/sla reused next head
    }
}

// ================= K4a: segment-local scan (MLP=8 prefetch) ==============
__global__ void k_scan_seg() {
    const int blk = blockIdx.x;
    const int bh = blk >> 4, seg = blk & (NSEG - 1);
    const int tid = threadIdx.x;       // 1024
    const size_t cbase = (size_t)bh * NCH + seg * CPS;
    float aq[CPS], sd[CPS];
#pragma unroll
    for (int j = 0; j < CPS; j++) aq[j] = __ldg(&g_aQ[cbase + j]);
#pragma unroll
    for (int j = 0; j < CPS; j++) sd[j] = g_Sd[(cbase + j) * 1024 + tid];
    float hloc = 0.f;
#pragma unroll
    for (int j = 0; j < CPS; j++) {
        g_h0[(cbase + j) * 1024 + tid] = hloc;
        hloc = aq[j] * hloc + sd[j];
    }
    g_segS[(size_t)blk * 1024 + tid] = hloc;
    if (tid == 0) {
        float p = 1.f;
#pragma unroll
        for (int j = 0; j < CPS; j++) p *= aq[j];
        g_segA[blk] = p;
    }
}

// ================= K4b: top-level segment scan (MLP=16 prefetch) =========
__global__ void k_scan_top() {
    const int bh = blockIdx.x;         // 64 blocks
    const int tid = threadIdx.x;       // 1024
    float sa[NSEG], ss[NSEG];
#pragma unroll
    for (int seg = 0; seg < NSEG; seg++) sa[seg] = __ldg(&g_segA[bh * NSEG + seg]);
#pragma unroll
    for (int seg = 0; seg < NSEG; seg++)
        ss[seg] = g_segS[((size_t)bh * NSEG + seg) * 1024 + tid];
    float carry = 0.f;
#pragma unroll
    for (int seg = 0; seg < NSEG; seg++) {
        g_segIn[((size_t)bh * NSEG + seg) * 1024 + tid] = carry;
        carry = sa[seg] * carry + ss[seg];
    }
}

// ================= K5: chunk output via tf32 MMA (fb epilogue) ===========
#define SXO 40   // ≡8 mod 32
#define SBC 36   // ≡4 mod 32
#define SGS 68   // ≡4 mod 32
#define CO_SMEM ((Q*SXO + Q*SBC + Q*SBC + HD*SBC + Q*SGS + 3*Q) * 4)

__global__ void k_chunk_output_mma(const float* __restrict__ Dp, int l) {
    extern __shared__ float sm[];
    float* sX  = sm;                     // [64][SXO]
    float* sB  = sX + Q * SXO;           // [64][SBC]
    float* sC  = sB + Q * SBC;           // [64][SBC]
    float* sh0 = sC + Q * SBC;           // [32][SBC]
    float* sG  = sh0 + HD * SBC;         // [64][SGS]
    float* sla = sG + Q * SGS;           // [64]
    float* sdt = sla + Q;                // [64]
    float* sE  = sdt + Q;                // [64]

    const int bx = blockIdx.x;
    const int ch = bx & (NCH - 1);
    const int h  = (bx >> 7) & 3;
    const int b  = bx >> 9;
    const int bhIdx = b * NH + h;
    const size_t base = (size_t)b * L_ + (size_t)ch * Q;
    const int tid = threadIdx.x;         // 256
    const int w = tid >> 5, lane = tid & 31;
    const int g = lane >> 2, tq = lane & 3;
    const int mrow = (w & 3) * 16;

    for (int idx = tid; idx < Q * 8; idx += 256) {
        int s = idx >> 3, jq = (idx & 7) * 4;
        float4 xv = *reinterpret_cast<const float4*>(&g_X [(base + s) * DI + h * HD + jq]);
        float4 bv = *reinterpret_cast<const float4*>(&g_Bm[(base + s) * DS + jq]);
        float4 cv = *reinterpret_cast<const float4*>(&g_Cm[(base + s) * DS + jq]);
        *reinterpret_cast<float4*>(&sX[s * SXO + jq]) = xv;
        *reinterpret_cast<float4*>(&sB[s * SBC + jq]) = bv;
        *reinterpret_cast<float4*>(&sC[s * SBC + jq]) = cv;
    }
    if (tid < Q) {
        float la = g_la[(base + tid) * NH + h];
        sla[tid] = la;
        sdt[tid] = g_dt[(base + tid) * NH + h];
        sE[tid] = __expf(la);
    }
    {
        float p = 1.f;
        int j0 = ch & (CPS - 1);
        size_t cb = (size_t)bhIdx * NCH + (size_t)(ch & ~(CPS - 1));
        for (int j = 0; j < j0; j++) p *= __ldg(&g_aQ[cb + j]);
        const int idx4 = tid * 4;
        const int seg = ch >> 3;
        const size_t sio = ((size_t)bhIdx * NSEG + seg) * 1024;
        float4 a = *reinterpret_cast<const float4*>(&g_h0[(size_t)bx * 1024 + idx4]);
        float4 si = *reinterpret_cast<const float4*>(&g_segIn[sio + idx4]);
        int pr = idx4 >> 5, j = idx4 & 31;
        float4 r;
        r.x = a.x + p * si.x; r.y = a.y + p * si.y;
        r.z = a.z + p * si.z; r.w = a.w + p * si.w;
        *reinterpret_cast<float4*>(&sh0[pr * SBC + j]) = r;
    }
    __syncthreads();

    // ---- Phase 1: G = C . B^T ----
    const int shalf = (w >> 2) * 32;
    float ga[4][4];
#pragma unroll
    for (int nt = 0; nt < 4; nt++)
#pragma unroll
        for (int j = 0; j < 4; j++) ga[nt][j] = 0.f;

#pragma unroll
    for (int k0 = 0; k0 < 32; k0 += 8) {
        unsigned ahi[4], alo[4];
        sp32(sC[(mrow + g) * SBC + k0 + tq],         ahi[0], alo[0]);
        sp32(sC[(mrow + g + 8) * SBC + k0 + tq],     ahi[1], alo[1]);
        sp32(sC[(mrow + g) * SBC + k0 + tq + 4],     ahi[2], alo[2]);
        sp32(sC[(mrow + g + 8) * SBC + k0 + tq + 4], ahi[3], alo[3]);
#pragma unroll
        for (int nt = 0; nt < 4; nt++) {
            int sc = shalf + nt * 8 + g;
            unsigned bhi[2], blo[2];
            sp32(sB[sc * SBC + k0 + tq],     bhi[0], blo[0]);
            sp32(sB[sc * SBC + k0 + tq + 4], bhi[1], blo[1]);
            mma_tf32(ga[nt], ahi, bhi);
            mma_tf32(ga[nt], ahi, blo);
            mma_tf32(ga[nt], alo, bhi);
        }
    }

    // ---- Phase 2: mask+exp into sG ----
#pragma unroll
    for (int nt = 0; nt < 4; nt++) {
        int s0 = shalf + nt * 8 + 2 * tq;
        int t0 = mrow + g, t1 = mrow + g + 8;
        float la0 = sla[t0], la1 = sla[t1];
        float d0 = sdt[s0], d1 = sdt[s0 + 1];
        float ls0 = sla[s0], ls1 = sla[s0 + 1];
        sG[t0 * SGS + s0]     = (s0 <= t0)     ? ga[nt][0] * d0 * __expf(la0 - ls0) : 0.f;
        sG[t0 * SGS + s0 + 1] = (s0 + 1 <= t0) ? ga[nt][1] * d1 * __expf(la0 - ls1) : 0.f;
        sG[t1 * SGS + s0]     = (s0 <= t1)     ? ga[nt][2] * d0 * __expf(la1 - ls0) : 0.f;
        sG[t1 * SGS + s0 + 1] = (s0 + 1 <= t1) ? ga[nt][3] * d1 * __expf(la1 - ls1) : 0.f;
    }
    __syncthreads();

    // ---- Phase 3: fa = G.X (k=64); fb = C.h0^T (k=32) ----
    const int phalf = (w >> 2) * 16;
    float fa[2][4], fb[2][4];
#pragma unroll
    for (int nt = 0; nt < 2; nt++)
#pragma unroll
        for (int j = 0; j < 4; j++) { fa[nt][j] = 0.f; fb[nt][j] = 0.f; }

#pragma unroll
    for (int k0 = 0; k0 < Q; k0 += 8) {
        unsigned ahi[4], alo[4];
        sp32(sG[(mrow + g) * SGS + k0 + tq],         ahi[0], alo[0]);
        sp32(sG[(mrow + g + 8) * SGS + k0 + tq],     ahi[1], alo[1]);
        sp32(sG[(mrow + g) * SGS + k0 + tq + 4],     ahi[2], alo[2]);
        sp32(sG[(mrow + g + 8) * SGS + k0 + tq + 4], ahi[3], alo[3]);
#pragma unroll
        for (int nt = 0; nt < 2; nt++) {
            int pc = phalf + nt * 8 + g;
            unsigned bhi[2], blo[2];
            sp32(sX[(k0 + tq) * SXO + pc],     bhi[0], blo[0]);
            sp32(sX[(k0 + tq + 4) * SXO + pc], bhi[1], blo[1]);
            mma_tf32(fa[nt], ahi, bhi);
            mma_tf32(fa[nt], ahi, blo);
            mma_tf32(fa[nt], alo, bhi);
        }
    }
#pragma unroll
    for (int k0 = 0; k0 < 32; k0 += 8) {
        unsigned ahi[4], alo[4];
        sp32(sC[(mrow + g) * SBC + k0 + tq],         ahi[0], alo[0]);
        sp32(sC[(mrow + g + 8) * SBC + k0 + tq],     ahi[1], alo[1]);
        sp32(sC[(mrow + g) * SBC + k0 + tq + 4],     ahi[2], alo[2]);
        sp32(sC[(mrow + g + 8) * SBC + k0 + tq + 4], ahi[3], alo[3]);
#pragma unroll
        for (int nt = 0; nt < 2; nt++) {
            int pc = phalf + nt * 8 + g;
            unsigned bhi[2], blo[2];
            sp32(sh0[pc * SBC + k0 + tq],     bhi[0], blo[0]);
            sp32(sh0[pc * SBC + k0 + tq + 4], bhi[1], blo[1]);
            mma_tf32(fb[nt], ahi, bhi);
            mma_tf32(fb[nt], ahi, blo);
            mma_tf32(fb[nt], alo, bhi);
        }
    }

    // ---- Epilogue: y = (fa + E_t*fb + D*x) * z ----
    const float Dh = Dp[l * NH + h];
    const float E0 = sE[mrow + g], E1 = sE[mrow + g + 8];
#pragma unroll
    for (int nt = 0; nt < 2; nt++) {
        int pc = phalf + nt * 8 + 2 * tq;
        {
            int t = mrow + g;
            size_t o = (base + t) * DI + h * HD + pc;
            float2 z = *reinterpret_cast<const float2*>(&g_Z[o]);
            float2 r;
            r.x = (fa[nt][0] + E0 * fb[nt][0] + Dh * sX[t * SXO + pc]) * z.x;
            r.y = (fa[nt][1] + E0 * fb[nt][1] + Dh * sX[t * SXO + pc + 1]) * z.y;
            *reinterpret_cast<float2*>(&g_y[o]) = r;
        }
        {
            int t = mrow + g + 8;
            size_t o = (base + t) * DI + h * HD + pc;
            float2 z = *reinterpret_cast<const float2*>(&g_Z[o]);
            float2 r;
            r.x = (fa[nt][2] + E1 * fb[nt][2] + Dh * sX[t * SXO + pc]) * z.x;
            r.y = (fa[nt][3] + E1 * fb[nt][3] + Dh * sX[t * SXO + pc + 1]) * z.y;
            *reinterpret_cast<float2*>(&g_y[o]) = r;
        }
    }
}

// ================= K6: out_proj via tf32 MMA + residual =================
#define OPM 128
#define SY_STRIDE 132    // ≡4 mod 32
#define OP_SMEM ((OPM * SY_STRIDE + DI * SW_STRIDE + 64) * 4)
__global__ void k_outproj_mma(const float* __restrict__ Wo,
                              const float* __restrict__ bo,
                              int l) {
    extern __shared__ float smem[];
    float* sY = smem;
    float* sW2 = sY + OPM * SY_STRIDE;
    float* sB2 = sW2 + DI * SW_STRIDE;

    const int row0 = blockIdx.x * OPM;
    const int tid = threadIdx.x;
    const int w = tid >> 5, lane = tid & 31;
    const int g = lane >> 2, tq = lane & 3;
    const float* Wl = Wo + (size_t)l * DI * DM;

    for (int idx = tid; idx < OPM * 32; idx += 256) {
        int r = idx >> 5, kq = (idx & 31) * 4;
        float4 v = *reinterpret_cast<const float4*>(&g_y[(size_t)(row0 + r) * DI + kq]);
        *reinterpret_cast<float4*>(&sY[r * SY_STRIDE + kq]) = v;
    }
    for (int idx = tid; idx < DI * 16; idx += 256) {
        int k = idx >> 4, nq = (idx & 15) * 4;
        float4 v = *reinterpret_cast<const float4*>(&Wl[(size_t)k * DM + nq]);
        *reinterpret_cast<float4*>(&sW2[k * SW_STRIDE + nq]) = v;
    }
    if (tid < 64) sB2[tid] = bo[l * DM + tid];
    __syncthreads();

    const int rA0 = (w * 16 + g) * SY_STRIDE;
    const int rA1 = (w * 16 + g + 8) * SY_STRIDE;

    float fa[8][4];
#pragma unroll
    for (int nt = 0; nt < 8; nt++)
#pragma unroll
        for (int j = 0; j < 4; j++) fa[nt][j] = 0.f;

#pragma unroll 4
    for (int k0 = 0; k0 < DI; k0 += 8) {
        unsigned ahi[4], alo[4];
        sp32(sY[rA0 + k0 + tq],     ahi[0], alo[0]);
        sp32(sY[rA1 + k0 + tq],     ahi[1], alo[1]);
        sp32(sY[rA0 + k0 + tq + 4], ahi[2], alo[2]);
        sp32(sY[rA1 + k0 + tq + 4], ahi[3], alo[3]);
#pragma unroll
        for (int nt = 0; nt < 8; nt++) {
            unsigned bhi[2], blo[2];
            sp32(sW2[(k0 + tq) * SW_STRIDE + nt * 8 + g],     bhi[0], blo[0]);
            sp32(sW2[(k0 + tq + 4) * SW_STRIDE + nt * 8 + g], bhi[1], blo[1]);
            mma_tf32(fa[nt], ahi, bhi);
            mma_tf32(fa[nt], ahi, blo);
            mma_tf32(fa[nt], alo, bhi);
        }
    }

#pragma unroll
    for (int nt = 0; nt < 8; nt++) {
        int c = nt * 8 + 2 * tq;
        float bc0 = sB2[c], bc1 = sB2[c + 1];
        int r0 = row0 + w * 16 + g;
#pragma unroll
        for (int half = 0; half < 2; half++) {
            int r = r0 + half * 8;
            size_t o = (size_t)r * DM + c;
            float2 hv = *reinterpret_cast<float2*>(&g_h[o]);
            hv.x += fa[nt][half * 2 + 0] + bc0;
            hv.y += fa[nt][half * 2 + 1] + bc1;
            *reinterpret_cast<float2*>(&g_h[o]) = hv;
        }
    }
}

// ================= K7a: pooling partial sums =================
__global__ void k_pool_a() {
    const int b = blockIdx.x >> 4, seg = blockIdx.x & 15;
    const int tid = threadIdx.x;   // 256
    const int d = tid & 63, part = tid >> 6;
    double s = 0.0;
    for (int ll = seg * 512 + part; ll < (seg + 1) * 512; ll += 4)
        s += (double)g_h[((size_t)b * L_ + ll) * DM + d];
    __shared__ double red[4][64];
    red[part][d] = s;
    __syncthreads();
    if (tid < 64)
        g_pool[((size_t)b * 16 + seg) * DM + tid] =
            red[0][tid] + red[1][tid] + red[2][tid] + red[3][tid];
}

// ================= K7b: combine + classifier =================
__global__ void k_pool_cls(const float* __restrict__ cW,
                           const float* __restrict__ cb,
                           float* __restrict__ out) {
    const int b = blockIdx.x;
    const int tid = threadIdx.x;   // 64
    __shared__ double pooled[64];
    double s = 0.0;
    for (int seg = 0; seg < 16; seg++)
        s += g_pool[((size_t)b * 16 + seg) * DM + tid];
    pooled[tid] = s / (double)L_;
    __syncthreads();
    if (tid < OUT_) {
        double acc = (double)cb[tid];
        for (int dd = 0; dd < DM; dd++)
            acc += pooled[dd] * (double)cW[dd * OUT_ + tid];
        out[b * OUT_ + tid] = (float)acc;
    }
}

// ================= launch =================
extern "C" void kernel_launch(void* const* d_in, const int* in_sizes, int n_in,
                              void* d_out, int out_size) {
    const float* x        = (const float*)d_in[0];
    const float* W_in     = (const float*)d_in[1];
    const float* b_in     = (const float*)d_in[2];
    const float* in_proj_W= (const float*)d_in[3];
    const float* in_proj_b= (const float*)d_in[4];
    const float* A_log    = (const float*)d_in[5];
    const float* Dp       = (const float*)d_in[6];
    const float* dt_bias  = (const float*)d_in[7];
    const float* out_proj_W = (const float*)d_in[8];
    const float* out_proj_b = (const float*)d_in[9];
    const float* cls_W    = (const float*)d_in[10];
    const float* cls_b    = (const float*)d_in[11];
    float* out = (float*)d_out;

    cudaFuncSetAttribute(k_inproj_mma, cudaFuncAttributeMaxDynamicSharedMemorySize, IP_SMEM);
    cudaFuncSetAttribute(k_outproj_mma, cudaFuncAttributeMaxDynamicSharedMemorySize, OP_SMEM);
    cudaFuncSetAttribute(k_chunk_output_mma, cudaFuncAttributeMaxDynamicSharedMemorySize, CO_SMEM);

    k_linear_in<<<BL / 16, 256>>>(x, W_in, b_in);
    for (int l = 0; l < NL; l++) {
        k_inproj_mma<<<BL / IPM, 256, IP_SMEM>>>(in_proj_W, in_proj_b, dt_bias, l);
        k_chunk_summary<<<B_ * NCH, 256>>>(A_log, l);
        k_scan_seg<<<B_ * NH * NSEG, 1024>>>();
        k_scan_top<<<B_ * NH, 1024>>>();
        k_chunk_output_mma<<<B_ * NH * NCH, 256, CO_SMEM>>>(Dp, l);
        k_outproj_mma<<<BL / OPM, 256, OP_SMEM>>>(out_proj_W, out_proj_b, l);
    }
    k_pool_a<<<B_ * 16, 256>>>();
    k_pool_cls<<<B_, 64>>>(cls_W, cls_b, out);
}

// round 15
// speedup vs baseline: 1.2048x; 1.0562x over previous
#include <cuda_runtime.h>
#include <cuda_bf16.h>
#include <cstdint>

// ---------------- problem constants ----------------
#define B_     16
#define L_     8192
#define IN_    57
#define DM     64
#define DS     32
#define HD     32
#define NH     4
#define DI     128          // EXP*DM
#define DPROJ  324          // 2*DI + 2*DS + NH
#define NL     2
#define OUT_   6
#define Q      64           // chunk length
#define NCH    (L_ / Q)     // 128 chunks
#define NSEG   16           // scan segments
#define CPS    (NCH / NSEG) // 8 chunks per segment
#define BL     (B_ * L_)    // 131072 rows

// ---------------- scratch (device globals; allocation-free) ----------------
__device__ float g_h [BL * DM];
__device__ float g_X [BL * DI];
__device__ float g_Z [BL * DI];
__device__ float g_y [BL * DI];
__device__ float g_Bm[BL * DS];
__device__ float g_Cm[BL * DS];
__device__ float g_dt[BL * NH];
__device__ float g_la[BL * NH];
__device__ float g_Sd[B_ * NH * NCH * HD * DS];    // chunk delta states
__device__ float g_h0[B_ * NH * NCH * HD * DS];    // segment-local entry states
__device__ float g_aQ[B_ * NH * NCH];              // chunk total decay
__device__ float g_segS[B_ * NH * NSEG * HD * DS]; // segment delta states
__device__ float g_segA[B_ * NH * NSEG];           // segment decay product
__device__ float g_segIn[B_ * NH * NSEG * HD * DS];// segment entry states
__device__ double g_pool[B_ * 16 * DM];

// ---------------- helpers ----------------
__device__ __forceinline__ float siluf(float v) { return v / (1.f + __expf(-v)); }
__device__ __forceinline__ float softplusf(float v) { return (v > 20.f) ? v : log1pf(__expf(v)); }

__device__ __forceinline__ unsigned cvt_tf32(float f) {
    unsigned u; asm("cvt.rna.tf32.f32 %0, %1;" : "=r"(u) : "f"(f)); return u;
}
__device__ __forceinline__ void sp32(float v, unsigned& h, unsigned& l) {
    h = cvt_tf32(v);
    l = cvt_tf32(v - __uint_as_float(h));
}
__device__ __forceinline__ void mma_tf32(float* d, const unsigned* a, const unsigned* b) {
    asm volatile("mma.sync.aligned.m16n8k8.row.col.f32.tf32.tf32.f32 "
                 "{%0,%1,%2,%3},{%4,%5,%6,%7},{%8,%9},{%0,%1,%2,%3};"
                 : "+f"(d[0]), "+f"(d[1]), "+f"(d[2]), "+f"(d[3])
                 : "r"(a[0]), "r"(a[1]), "r"(a[2]), "r"(a[3]),
                   "r"(b[0]), "r"(b[1]));
}

// ================= K1: linear_in  h = x @ W_in + b_in =================
__global__ void k_linear_in(const float* __restrict__ x,
                            const float* __restrict__ W,
                            const float* __restrict__ bias) {
    const int row0 = blockIdx.x * 16;
    __shared__ float sx[16][IN_ + 1];
    const int tid = threadIdx.x;
    for (int idx = tid; idx < 16 * IN_; idx += 256) {
        int r = idx / IN_, k = idx % IN_;
        sx[r][k] = x[(size_t)(row0 + r) * IN_ + k];
    }
    __syncthreads();
    const int c = tid & 63, q = tid >> 6;
    float bc = bias[c];
    float acc[4] = {bc, bc, bc, bc};
    for (int k = 0; k < IN_; k++) {
        float wv = __ldg(&W[k * DM + c]);
#pragma unroll
        for (int j = 0; j < 4; j++) acc[j] += sx[q * 4 + j][k] * wv;
    }
#pragma unroll
    for (int j = 0; j < 4; j++)
        g_h[(size_t)(row0 + q * 4 + j) * DM + c] = acc[j];
}

// ================= K2: in_proj via tf32 MMA (double-buffered W) ==========
#define IPM 128
#define SH_STRIDE 68     // ≡4 mod 32: A-operand conflict-free
#define SW_STRIDE 72     // ≡8 mod 32: B-operand conflict-free
#define IP_SMEM ((IPM * SH_STRIDE + 2 * 64 * SW_STRIDE + 384) * 4)

__device__ __forceinline__ void ip_store(int row, int c, float v0, float v1,
                                         const float* __restrict__ dtb) {
    size_t r = (size_t)row;
    if (c < DI) {
        *reinterpret_cast<float2*>(&g_Z[r * DI + c]) = make_float2(siluf(v0), siluf(v1));
    } else if (c < 2 * DI) {
        *reinterpret_cast<float2*>(&g_X[r * DI + (c - DI)]) = make_float2(siluf(v0), siluf(v1));
    } else if (c < 2 * DI + DS) {
        *reinterpret_cast<float2*>(&g_Bm[r * DS + (c - 2 * DI)]) = make_float2(siluf(v0), siluf(v1));
    } else if (c < 2 * DI + 2 * DS) {
        *reinterpret_cast<float2*>(&g_Cm[r * DS + (c - 2 * DI - DS)]) = make_float2(siluf(v0), siluf(v1));
    } else {
        int hh = c - (2 * DI + 2 * DS);
        *reinterpret_cast<float2*>(&g_dt[r * NH + hh]) =
            make_float2(softplusf(v0 + __ldg(&dtb[hh])), softplusf(v1 + __ldg(&dtb[hh + 1])));
    }
}

__global__ void k_inproj_mma(const float* __restrict__ W,
                             const float* __restrict__ bias,
                             const float* __restrict__ dt_bias,
                             int l) {
    extern __shared__ float smem[];
    float* sH = smem;                        // IPM x SH_STRIDE
    float* sW0 = sH + IPM * SH_STRIDE;       // 64 x SW_STRIDE
    float* sW1 = sW0 + 64 * SW_STRIDE;       // 64 x SW_STRIDE
    float* sBias = sW1 + 64 * SW_STRIDE;     // 384

    const int row0 = blockIdx.x * IPM;
    const int tid = threadIdx.x;
    const int w = tid >> 5, lane = tid & 31;
    const int g = lane >> 2, tq = lane & 3;
    const float* Wl = W + (size_t)l * DM * DPROJ;
    const float* dtb = dt_bias + l * NH;

    const int wn = tid & 63, wkhi = tid >> 6;
    float wr[16];

    {
        int c = wn;  // chunk 0
#pragma unroll
        for (int i = 0; i < 16; i++)
            wr[i] = __ldg(&Wl[(size_t)(4 * i + wkhi) * DPROJ + c]);
    }
    for (int idx = tid; idx < IPM * 16; idx += 256) {
        int r = idx >> 4, kq = (idx & 15) * 4;
        float4 v = *reinterpret_cast<const float4*>(&g_h[(size_t)(row0 + r) * DM + kq]);
        *reinterpret_cast<float4*>(&sH[r * SH_STRIDE + kq]) = v;
    }
    for (int idx = tid; idx < 384; idx += 256)
        sBias[idx] = (idx < DPROJ) ? bias[l * DPROJ + idx] : 0.f;
#pragma unroll
    for (int i = 0; i < 16; i++)
        sW0[(4 * i + wkhi) * SW_STRIDE + wn] = wr[i];
    __syncthreads();

    const int rA0 = (w * 16 + g) * SH_STRIDE;
    const int rA1 = (w * 16 + g + 8) * SH_STRIDE;

    for (int chunk = 0; chunk < 6; chunk++) {
        float* sWc = (chunk & 1) ? sW1 : sW0;
        float* sWn = (chunk & 1) ? sW0 : sW1;

        if (chunk < 5) {
            int c = (chunk + 1) * 64 + wn;
            bool ok = c < DPROJ;
#pragma unroll
            for (int i = 0; i < 16; i++)
                wr[i] = ok ? __ldg(&Wl[(size_t)(4 * i + wkhi) * DPROJ + c]) : 0.f;
        }

        float fa[8][4];
#pragma unroll
        for (int nt = 0; nt < 8; nt++)
#pragma unroll
            for (int j = 0; j < 4; j++) fa[nt][j] = 0.f;

#pragma unroll
        for (int k0 = 0; k0 < 64; k0 += 8) {
            unsigned ahi[4], alo[4];
            sp32(sH[rA0 + k0 + tq],     ahi[0], alo[0]);
            sp32(sH[rA1 + k0 + tq],     ahi[1], alo[1]);
            sp32(sH[rA0 + k0 + tq + 4], ahi[2], alo[2]);
            sp32(sH[rA1 + k0 + tq + 4], ahi[3], alo[3]);
#pragma unroll
            for (int nt = 0; nt < 8; nt++) {
                unsigned bhi[2], blo[2];
                sp32(sWc[(k0 + tq) * SW_STRIDE + nt * 8 + g],     bhi[0], blo[0]);
                sp32(sWc[(k0 + tq + 4) * SW_STRIDE + nt * 8 + g], bhi[1], blo[1]);
                mma_tf32(fa[nt], ahi, bhi);
                mma_tf32(fa[nt], ahi, blo);
                mma_tf32(fa[nt], alo, bhi);
            }
        }

#pragma unroll
        for (int nt = 0; nt < 8; nt++) {
            int cg = chunk * 64 + nt * 8 + 2 * tq;
            if (cg >= DPROJ) continue;
            float b0v = sBias[cg], b1v = sBias[cg + 1];
            int r0 = row0 + w * 16 + g;
            ip_store(r0,     cg, fa[nt][0] + b0v, fa[nt][1] + b1v, dtb);
            ip_store(r0 + 8, cg, fa[nt][2] + b0v, fa[nt][3] + b1v, dtb);
        }

        if (chunk < 5) {
#pragma unroll
            for (int i = 0; i < 16; i++)
                sWn[(4 * i + wkhi) * SW_STRIDE + wn] = wr[i];
            __syncthreads();
        }
    }
}

// ================= K3: per-chunk summary (R13 per-head, validated) =======
#define CS_STRIDE 34
__global__ void k_chunk_summary(const float* __restrict__ A_log, int l) {
    const int bx = blockIdx.x;
    const int ch = bx & (NCH - 1);
    const int h  = (bx >> 7) & 3;
    const int b  = bx >> 9;
    const size_t base = (size_t)b * L_ + (size_t)ch * Q;
    __shared__ __align__(16) float sX[Q * CS_STRIDE];
    __shared__ __align__(16) float sB[Q * CS_STRIDE];
    __shared__ float sla[Q], sw_[Q], sdt[Q];
    const int tid = threadIdx.x;               // 256 threads

    for (int idx = tid; idx < Q * 8; idx += 256) {
        int s = idx >> 3, jq = (idx & 7) * 4;
        float4 xv = *reinterpret_cast<const float4*>(&g_X [(base + s) * DI + h * HD + jq]);
        float4 bv = *reinterpret_cast<const float4*>(&g_Bm[(base + s) * DS + jq]);
        sX[s * CS_STRIDE + jq]     = xv.x; sX[s * CS_STRIDE + jq + 1] = xv.y;
        sX[s * CS_STRIDE + jq + 2] = xv.z; sX[s * CS_STRIDE + jq + 3] = xv.w;
        sB[s * CS_STRIDE + jq]     = bv.x; sB[s * CS_STRIDE + jq + 1] = bv.y;
        sB[s * CS_STRIDE + jq + 2] = bv.z; sB[s * CS_STRIDE + jq + 3] = bv.w;
    }
    if (tid < Q) sdt[tid] = g_dt[(base + tid) * NH + h];
    __syncthreads();

    const float A = -expf(A_log[l * NH + h]);
    if (tid < Q) {
        float v = sdt[tid] * A;
#pragma unroll
        for (int o = 1; o < 32; o <<= 1) {
            float u = __shfl_up_sync(0xffffffffu, v, o);
            if ((tid & 31) >= o) v += u;
        }
        sla[tid] = v;
    }
    __syncthreads();
    if (tid >= 32 && tid < 64) sla[tid] += sla[31];
    __syncthreads();
    const float laQ = sla[Q - 1];
    if (tid < Q) {
        g_la[(base + tid) * NH + h] = sla[tid];
        sw_[tid] = sdt[tid] * __expf(laQ - sla[tid]);
    }
    __syncthreads();
    for (int idx = tid; idx < Q * HD; idx += 256) {
        int s = idx >> 5;
        sX[s * CS_STRIDE + (idx & 31)] *= sw_[s];
    }
    __syncthreads();

    const int p0 = (tid >> 4) * 2, n0 = (tid & 15) * 2;
    float a00 = 0.f, a01 = 0.f, a10 = 0.f, a11 = 0.f;
#pragma unroll 8
    for (int s = 0; s < Q; s++) {
        float2 xv = *reinterpret_cast<const float2*>(&sX[s * CS_STRIDE + p0]);
        float2 bv = *reinterpret_cast<const float2*>(&sB[s * CS_STRIDE + n0]);
        a00 += xv.x * bv.x; a01 += xv.x * bv.y;
        a10 += xv.y * bv.x; a11 += xv.y * bv.y;
    }
    float* dst = &g_Sd[(size_t)bx * 1024];
    *reinterpret_cast<float2*>(&dst[p0 * 32 + n0])       = make_float2(a00, a01);
    *reinterpret_cast<float2*>(&dst[(p0 + 1) * 32 + n0]) = make_float2(a10, a11);
    if (tid == 0) g_aQ[bx] = __expf(laQ);
}

// ================= K4a: segment-local scan (MLP=8 prefetch) ==============
__global__ void k_scan_seg() {
    const int blk = blockIdx.x;
    const int bh = blk >> 4, seg = blk & (NSEG - 1);
    const int tid = threadIdx.x;       // 1024
    const size_t cbase = (size_t)bh * NCH + seg * CPS;
    float aq[CPS], sd[CPS];
#pragma unroll
    for (int j = 0; j < CPS; j++) aq[j] = __ldg(&g_aQ[cbase + j]);
#pragma unroll
    for (int j = 0; j < CPS; j++) sd[j] = g_Sd[(cbase + j) * 1024 + tid];
    float hloc = 0.f;
#pragma unroll
    for (int j = 0; j < CPS; j++) {
        g_h0[(cbase + j) * 1024 + tid] = hloc;
        hloc = aq[j] * hloc + sd[j];
    }
    g_segS[(size_t)blk * 1024 + tid] = hloc;
    if (tid == 0) {
        float p = 1.f;
#pragma unroll
        for (int j = 0; j < CPS; j++) p *= aq[j];
        g_segA[blk] = p;
    }
}

// ================= K4b: top-level segment scan (MLP=16 prefetch) =========
__global__ void k_scan_top() {
    const int bh = blockIdx.x;         // 64 blocks
    const int tid = threadIdx.x;       // 1024
    float sa[NSEG], ss[NSEG];
#pragma unroll
    for (int seg = 0; seg < NSEG; seg++) sa[seg] = __ldg(&g_segA[bh * NSEG + seg]);
#pragma unroll
    for (int seg = 0; seg < NSEG; seg++)
        ss[seg] = g_segS[((size_t)bh * NSEG + seg) * 1024 + tid];
    float carry = 0.f;
#pragma unroll
    for (int seg = 0; seg < NSEG; seg++) {
        g_segIn[((size_t)bh * NSEG + seg) * 1024 + tid] = carry;
        carry = sa[seg] * carry + ss[seg];
    }
}

// ================= K5: chunk output via tf32 MMA (fb epilogue) ===========
#define SXO 40   // ≡8 mod 32
#define SBC 36   // ≡4 mod 32
#define SGS 68   // ≡4 mod 32
#define CO_SMEM ((Q*SXO + Q*SBC + Q*SBC + HD*SBC + Q*SGS + 3*Q) * 4)

__global__ void k_chunk_output_mma(const float* __restrict__ Dp, int l) {
    extern __shared__ float sm[];
    float* sX  = sm;                     // [64][SXO]
    float* sB  = sX + Q * SXO;           // [64][SBC]
    float* sC  = sB + Q * SBC;           // [64][SBC]
    float* sh0 = sC + Q * SBC;           // [32][SBC]
    float* sG  = sh0 + HD * SBC;         // [64][SGS]
    float* sla = sG + Q * SGS;           // [64]
    float* sdt = sla + Q;                // [64]
    float* sE  = sdt + Q;                // [64]

    const int bx = blockIdx.x;
    const int ch = bx & (NCH - 1);
    const int h  = (bx >> 7) & 3;
    const int b  = bx >> 9;
    const int bhIdx = b * NH + h;
    const size_t base = (size_t)b * L_ + (size_t)ch * Q;
    const int tid = threadIdx.x;         // 256
    const int w = tid >> 5, lane = tid & 31;
    const int g = lane >> 2, tq = lane & 3;
    const int mrow = (w & 3) * 16;

    for (int idx = tid; idx < Q * 8; idx += 256) {
        int s = idx >> 3, jq = (idx & 7) * 4;
        float4 xv = *reinterpret_cast<const float4*>(&g_X [(base + s) * DI + h * HD + jq]);
        float4 bv = *reinterpret_cast<const float4*>(&g_Bm[(base + s) * DS + jq]);
        float4 cv = *reinterpret_cast<const float4*>(&g_Cm[(base + s) * DS + jq]);
        *reinterpret_cast<float4*>(&sX[s * SXO + jq]) = xv;
        *reinterpret_cast<float4*>(&sB[s * SBC + jq]) = bv;
        *reinterpret_cast<float4*>(&sC[s * SBC + jq]) = cv;
    }
    if (tid < Q) {
        float la = g_la[(base + tid) * NH + h];
        sla[tid] = la;
        sdt[tid] = g_dt[(base + tid) * NH + h];
        sE[tid] = __expf(la);
    }
    {
        float p = 1.f;
        int j0 = ch & (CPS - 1);
        size_t cb = (size_t)bhIdx * NCH + (size_t)(ch & ~(CPS - 1));
        for (int j = 0; j < j0; j++) p *= __ldg(&g_aQ[cb + j]);
        const int idx4 = tid * 4;
        const int seg = ch >> 3;
        const size_t sio = ((size_t)bhIdx * NSEG + seg) * 1024;
        float4 a = *reinterpret_cast<const float4*>(&g_h0[(size_t)bx * 1024 + idx4]);
        float4 si = *reinterpret_cast<const float4*>(&g_segIn[sio + idx4]);
        int pr = idx4 >> 5, j = idx4 & 31;
        float4 r;
        r.x = a.x + p * si.x; r.y = a.y + p * si.y;
        r.z = a.z + p * si.z; r.w = a.w + p * si.w;
        *reinterpret_cast<float4*>(&sh0[pr * SBC + j]) = r;
    }
    __syncthreads();

    // ---- Phase 1: G = C . B^T ----
    const int shalf = (w >> 2) * 32;
    float ga[4][4];
#pragma unroll
    for (int nt = 0; nt < 4; nt++)
#pragma unroll
        for (int j = 0; j < 4; j++) ga[nt][j] = 0.f;

#pragma unroll
    for (int k0 = 0; k0 < 32; k0 += 8) {
        unsigned ahi[4], alo[4];
        sp32(sC[(mrow + g) * SBC + k0 + tq],         ahi[0], alo[0]);
        sp32(sC[(mrow + g + 8) * SBC + k0 + tq],     ahi[1], alo[1]);
        sp32(sC[(mrow + g) * SBC + k0 + tq + 4],     ahi[2], alo[2]);
        sp32(sC[(mrow + g + 8) * SBC + k0 + tq + 4], ahi[3], alo[3]);
#pragma unroll
        for (int nt = 0; nt < 4; nt++) {
            int sc = shalf + nt * 8 + g;
            unsigned bhi[2], blo[2];
            sp32(sB[sc * SBC + k0 + tq],     bhi[0], blo[0]);
            sp32(sB[sc * SBC + k0 + tq + 4], bhi[1], blo[1]);
            mma_tf32(ga[nt], ahi, bhi);
            mma_tf32(ga[nt], ahi, blo);
            mma_tf32(ga[nt], alo, bhi);
        }
    }

    // ---- Phase 2: mask+exp into sG ----
#pragma unroll
    for (int nt = 0; nt < 4; nt++) {
        int s0 = shalf + nt * 8 + 2 * tq;
        int t0 = mrow + g, t1 = mrow + g + 8;
        float la0 = sla[t0], la1 = sla[t1];
        float d0 = sdt[s0], d1 = sdt[s0 + 1];
        float ls0 = sla[s0], ls1 = sla[s0 + 1];
        sG[t0 * SGS + s0]     = (s0 <= t0)     ? ga[nt][0] * d0 * __expf(la0 - ls0) : 0.f;
        sG[t0 * SGS + s0 + 1] = (s0 + 1 <= t0) ? ga[nt][1] * d1 * __expf(la0 - ls1) : 0.f;
        sG[t1 * SGS + s0]     = (s0 <= t1)     ? ga[nt][2] * d0 * __expf(la1 - ls0) : 0.f;
        sG[t1 * SGS + s0 + 1] = (s0 + 1 <= t1) ? ga[nt][3] * d1 * __expf(la1 - ls1) : 0.f;
    }
    __syncthreads();

    // ---- Phase 3: fa = G.X (k=64); fb = C.h0^T (k=32) ----
    const int phalf = (w >> 2) * 16;
    float fa[2][4], fb[2][4];
#pragma unroll
    for (int nt = 0; nt < 2; nt++)
#pragma unroll
        for (int j = 0; j < 4; j++) { fa[nt][j] = 0.f; fb[nt][j] = 0.f; }

#pragma unroll
    for (int k0 = 0; k0 < Q; k0 += 8) {
        unsigned ahi[4], alo[4];
        sp32(sG[(mrow + g) * SGS + k0 + tq],         ahi[0], alo[0]);
        sp32(sG[(mrow + g + 8) * SGS + k0 + tq],     ahi[1], alo[1]);
        sp32(sG[(mrow + g) * SGS + k0 + tq + 4],     ahi[2], alo[2]);
        sp32(sG[(mrow + g + 8) * SGS + k0 + tq + 4], ahi[3], alo[3]);
#pragma unroll
        for (int nt = 0; nt < 2; nt++) {
            int pc = phalf + nt * 8 + g;
            unsigned bhi[2], blo[2];
            sp32(sX[(k0 + tq) * SXO + pc],     bhi[0], blo[0]);
            sp32(sX[(k0 + tq + 4) * SXO + pc], bhi[1], blo[1]);
            mma_tf32(fa[nt], ahi, bhi);
            mma_tf32(fa[nt], ahi, blo);
            mma_tf32(fa[nt], alo, bhi);
        }
    }
#pragma unroll
    for (int k0 = 0; k0 < 32; k0 += 8) {
        unsigned ahi[4], alo[4];
        sp32(sC[(mrow + g) * SBC + k0 + tq],         ahi[0], alo[0]);
        sp32(sC[(mrow + g + 8) * SBC + k0 + tq],     ahi[1], alo[1]);
        sp32(sC[(mrow + g) * SBC + k0 + tq + 4],     ahi[2], alo[2]);
        sp32(sC[(mrow + g + 8) * SBC + k0 + tq + 4], ahi[3], alo[3]);
#pragma unroll
        for (int nt = 0; nt < 2; nt++) {
            int pc = phalf + nt * 8 + g;
            unsigned bhi[2], blo[2];
            sp32(sh0[pc * SBC + k0 + tq],     bhi[0], blo[0]);
            sp32(sh0[pc * SBC + k0 + tq + 4], bhi[1], blo[1]);
            mma_tf32(fb[nt], ahi, bhi);
            mma_tf32(fb[nt], ahi, blo);
            mma_tf32(fb[nt], alo, bhi);
        }
    }

    // ---- Epilogue: y = (fa + E_t*fb + D*x) * z ----
    const float Dh = Dp[l * NH + h];
    const float E0 = sE[mrow + g], E1 = sE[mrow + g + 8];
#pragma unroll
    for (int nt = 0; nt < 2; nt++) {
        int pc = phalf + nt * 8 + 2 * tq;
        {
            int t = mrow + g;
            size_t o = (base + t) * DI + h * HD + pc;
            float2 z = *reinterpret_cast<const float2*>(&g_Z[o]);
            float2 r;
            r.x = (fa[nt][0] + E0 * fb[nt][0] + Dh * sX[t * SXO + pc]) * z.x;
            r.y = (fa[nt][1] + E0 * fb[nt][1] + Dh * sX[t * SXO + pc + 1]) * z.y;
            *reinterpret_cast<float2*>(&g_y[o]) = r;
        }
        {
            int t = mrow + g + 8;
            size_t o = (base + t) * DI + h * HD + pc;
            float2 z = *reinterpret_cast<const float2*>(&g_Z[o]);
            float2 r;
            r.x = (fa[nt][2] + E1 * fb[nt][2] + Dh * sX[t * SXO + pc]) * z.x;
            r.y = (fa[nt][3] + E1 * fb[nt][3] + Dh * sX[t * SXO + pc + 1]) * z.y;
            *reinterpret_cast<float2*>(&g_y[o]) = r;
        }
    }
}

// ================= K6: out_proj via tf32 MMA + residual (OPM=64) =========
#define OPM 64
#define SY_STRIDE 132    // ≡4 mod 32
#define OP_SMEM ((OPM * SY_STRIDE + DI * SW_STRIDE + 64) * 4)
__global__ void k_outproj_mma(const float* __restrict__ Wo,
                              const float* __restrict__ bo,
                              int l) {
    extern __shared__ float smem[];
    float* sY = smem;
    float* sW2 = sY + OPM * SY_STRIDE;
    float* sB2 = sW2 + DI * SW_STRIDE;

    const int row0 = blockIdx.x * OPM;
    const int tid = threadIdx.x;
    const int w = tid >> 5, lane = tid & 31;
    const int g = lane >> 2, tq = lane & 3;
    const int mrow = (w & 3) * 16;
    const int nhalf = (w >> 2) * 32;
    const float* Wl = Wo + (size_t)l * DI * DM;

    for (int idx = tid; idx < OPM * 32; idx += 256) {
        int r = idx >> 5, kq = (idx & 31) * 4;
        float4 v = *reinterpret_cast<const float4*>(&g_y[(size_t)(row0 + r) * DI + kq]);
        *reinterpret_cast<float4*>(&sY[r * SY_STRIDE + kq]) = v;
    }
    for (int idx = tid; idx < DI * 16; idx += 256) {
        int k = idx >> 4, nq = (idx & 15) * 4;
        float4 v = *reinterpret_cast<const float4*>(&Wl[(size_t)k * DM + nq]);
        *reinterpret_cast<float4*>(&sW2[k * SW_STRIDE + nq]) = v;
    }
    if (tid < 64) sB2[tid] = bo[l * DM + tid];
    __syncthreads();

    const int rA0 = (mrow + g) * SY_STRIDE;
    const int rA1 = (mrow + g + 8) * SY_STRIDE;

    float fa[4][4];
#pragma unroll
    for (int nt = 0; nt < 4; nt++)
#pragma unroll
        for (int j = 0; j < 4; j++) fa[nt][j] = 0.f;

#pragma unroll 4
    for (int k0 = 0; k0 < DI; k0 += 8) {
        unsigned ahi[4], alo[4];
        sp32(sY[rA0 + k0 + tq],     ahi[0], alo[0]);
        sp32(sY[rA1 + k0 + tq],     ahi[1], alo[1]);
        sp32(sY[rA0 + k0 + tq + 4], ahi[2], alo[2]);
        sp32(sY[rA1 + k0 + tq + 4], ahi[3], alo[3]);
#pragma unroll
        for (int nt = 0; nt < 4; nt++) {
            unsigned bhi[2], blo[2];
            sp32(sW2[(k0 + tq) * SW_STRIDE + nhalf + nt * 8 + g],     bhi[0], blo[0]);
            sp32(sW2[(k0 + tq + 4) * SW_STRIDE + nhalf + nt * 8 + g], bhi[1], blo[1]);
            mma_tf32(fa[nt], ahi, bhi);
            mma_tf32(fa[nt], ahi, blo);
            mma_tf32(fa[nt], alo, bhi);
        }
    }

#pragma unroll
    for (int nt = 0; nt < 4; nt++) {
        int c = nhalf + nt * 8 + 2 * tq;
        float bc0 = sB2[c], bc1 = sB2[c + 1];
#pragma unroll
        for (int half = 0; half < 2; half++) {
            int r = row0 + mrow + g + half * 8;
            size_t o = (size_t)r * DM + c;
            float2 hv = *reinterpret_cast<float2*>(&g_h[o]);
            hv.x += fa[nt][half * 2 + 0] + bc0;
            hv.y += fa[nt][half * 2 + 1] + bc1;
            *reinterpret_cast<float2*>(&g_h[o]) = hv;
        }
    }
}

// ================= K7a: pooling partial sums =================
__global__ void k_pool_a() {
    const int b = blockIdx.x >> 4, seg = blockIdx.x & 15;
    const int tid = threadIdx.x;   // 256
    const int d = tid & 63, part = tid >> 6;
    double s = 0.0;
    for (int ll = seg * 512 + part; ll < (seg + 1) * 512; ll += 4)
        s += (double)g_h[((size_t)b * L_ + ll) * DM + d];
    __shared__ double red[4][64];
    red[part][d] = s;
    __syncthreads();
    if (tid < 64)
        g_pool[((size_t)b * 16 + seg) * DM + tid] =
            red[0][tid] + red[1][tid] + red[2][tid] + red[3][tid];
}

// ================= K7b: combine + classifier =================
__global__ void k_pool_cls(const float* __restrict__ cW,
                           const float* __restrict__ cb,
                           float* __restrict__ out) {
    const int b = blockIdx.x;
    const int tid = threadIdx.x;   // 64
    __shared__ double pooled[64];
    double s = 0.0;
    for (int seg = 0; seg < 16; seg++)
        s += g_pool[((size_t)b * 16 + seg) * DM + tid];
    pooled[tid] = s / (double)L_;
    __syncthreads();
    if (tid < OUT_) {
        double acc = (double)cb[tid];
        for (int dd = 0; dd < DM; dd++)
            acc += pooled[dd] * (double)cW[dd * OUT_ + tid];
        out[b * OUT_ + tid] = (float)acc;
    }
}

// ================= launch =================
extern "C" void kernel_launch(void* const* d_in, const int* in_sizes, int n_in,
                              void* d_out, int out_size) {
    const float* x        = (const float*)d_in[0];
    const float* W_in     = (const float*)d_in[1];
    const float* b_in     = (const float*)d_in[2];
    const float* in_proj_W= (const float*)d_in[3];
    const float* in_proj_b= (const float*)d_in[4];
    const float* A_log    = (const float*)d_in[5];
    const float* Dp       = (const float*)d_in[6];
    const float* dt_bias  = (const float*)d_in[7];
    const float* out_proj_W = (const float*)d_in[8];
    const float* out_proj_b = (const float*)d_in[9];
    const float* cls_W    = (const float*)d_in[10];
    const float* cls_b    = (const float*)d_in[11];
    float* out = (float*)d_out;

    cudaFuncSetAttribute(k_inproj_mma, cudaFuncAttributeMaxDynamicSharedMemorySize, IP_SMEM);
    cudaFuncSetAttribute(k_outproj_mma, cudaFuncAttributeMaxDynamicSharedMemorySize, OP_SMEM);
    cudaFuncSetAttribute(k_chunk_output_mma, cudaFuncAttributeMaxDynamicSharedMemorySize, CO_SMEM);

    k_linear_in<<<BL / 16, 256>>>(x, W_in, b_in);
    for (int l = 0; l < NL; l++) {
        k_inproj_mma<<<BL / IPM, 256, IP_SMEM>>>(in_proj_W, in_proj_b, dt_bias, l);
        k_chunk_summary<<<B_ * NH * NCH, 256>>>(A_log, l);
        k_scan_seg<<<B_ * NH * NSEG, 1024>>>();
        k_scan_top<<<B_ * NH, 1024>>>();
        k_chunk_output_mma<<<B_ * NH * NCH, 256, CO_SMEM>>>(Dp, l);
        k_outproj_mma<<<BL / OPM, 256, OP_SMEM>>>(out_proj_W, out_proj_b, l);
    }
    k_pool_a<<<B_ * 16, 256>>>();
    k_pool_cls<<<B_, 64>>>(cls_W, cls_b, out);
}

// round 16
// speedup vs baseline: 1.2803x; 1.0627x over previous
#include <cuda_runtime.h>
#include <cuda_bf16.h>
#include <cstdint>

// ---------------- problem constants ----------------
#define B_     16
#define L_     8192
#define IN_    57
#define DM     64
#define DS     32
#define HD     32
#define NH     4
#define DI     128          // EXP*DM
#define DPROJ  324          // 2*DI + 2*DS + NH
#define NL     2
#define OUT_   6
#define Q      64           // chunk length
#define NCH    (L_ / Q)     // 128 chunks
#define NSEG   16           // scan segments
#define CPS    (NCH / NSEG) // 8 chunks per segment
#define BL     (B_ * L_)    // 131072 rows

// ---------------- scratch (device globals; allocation-free) ----------------
__device__ float g_h [BL * DM];
__device__ float g_X [BL * DI];
__device__ float g_Z [BL * DI];
__device__ float g_y [BL * DI];
__device__ float g_Bm[BL * DS];
__device__ float g_Cm[BL * DS];
__device__ float g_dt[BL * NH];
__device__ float g_la[BL * NH];
__device__ float g_Sd[B_ * NH * NCH * HD * DS];    // chunk delta states
__device__ float g_h0[B_ * NH * NCH * HD * DS];    // segment-local entry states
__device__ float g_aQ[B_ * NH * NCH];              // chunk total decay
__device__ float g_segS[B_ * NH * NSEG * HD * DS]; // segment delta states
__device__ float g_segA[B_ * NH * NSEG];           // segment decay product
__device__ float g_segIn[B_ * NH * NSEG * HD * DS];// segment entry states
__device__ double g_pool[B_ * 16 * DM];

// ---------------- helpers ----------------
__device__ __forceinline__ float siluf(float v) { return v / (1.f + __expf(-v)); }
__device__ __forceinline__ float softplusf(float v) { return (v > 20.f) ? v : log1pf(__expf(v)); }

__device__ __forceinline__ unsigned cvt_tf32(float f) {
    unsigned u; asm("cvt.rna.tf32.f32 %0, %1;" : "=r"(u) : "f"(f)); return u;
}
__device__ __forceinline__ void sp32(float v, unsigned& h, unsigned& l) {
    h = cvt_tf32(v);
    l = cvt_tf32(v - __uint_as_float(h));
}
__device__ __forceinline__ void mma_tf32(float* d, const unsigned* a, const unsigned* b) {
    asm volatile("mma.sync.aligned.m16n8k8.row.col.f32.tf32.tf32.f32 "
                 "{%0,%1,%2,%3},{%4,%5,%6,%7},{%8,%9},{%0,%1,%2,%3};"
                 : "+f"(d[0]), "+f"(d[1]), "+f"(d[2]), "+f"(d[3])
                 : "r"(a[0]), "r"(a[1]), "r"(a[2]), "r"(a[3]),
                   "r"(b[0]), "r"(b[1]));
}

// ================= K1: linear_in  h = x @ W_in + b_in =================
__global__ void k_linear_in(const float* __restrict__ x,
                            const float* __restrict__ W,
                            const float* __restrict__ bias) {
    const int row0 = blockIdx.x * 16;
    __shared__ float sx[16][IN_ + 1];
    const int tid = threadIdx.x;
    for (int idx = tid; idx < 16 * IN_; idx += 256) {
        int r = idx / IN_, k = idx % IN_;
        sx[r][k] = x[(size_t)(row0 + r) * IN_ + k];
    }
    __syncthreads();
    const int c = tid & 63, q = tid >> 6;
    float bc = bias[c];
    float acc[4] = {bc, bc, bc, bc};
    for (int k = 0; k < IN_; k++) {
        float wv = __ldg(&W[k * DM + c]);
#pragma unroll
        for (int j = 0; j < 4; j++) acc[j] += sx[q * 4 + j][k] * wv;
    }
#pragma unroll
    for (int j = 0; j < 4; j++)
        g_h[(size_t)(row0 + q * 4 + j) * DM + c] = acc[j];
}

// ================= K2: in_proj via tf32 MMA (IPM=64, double-buffered W) ==
#define IPM 64
#define SH_STRIDE 68     // ≡4 mod 32: A-operand conflict-free
#define SW_STRIDE 72     // ≡8 mod 32: B-operand conflict-free
#define IP_SMEM ((IPM * SH_STRIDE + 2 * 64 * SW_STRIDE + 384) * 4)

__device__ __forceinline__ void ip_store(int row, int c, float v0, float v1,
                                         const float* __restrict__ dtb) {
    size_t r = (size_t)row;
    if (c < DI) {
        *reinterpret_cast<float2*>(&g_Z[r * DI + c]) = make_float2(siluf(v0), siluf(v1));
    } else if (c < 2 * DI) {
        *reinterpret_cast<float2*>(&g_X[r * DI + (c - DI)]) = make_float2(siluf(v0), siluf(v1));
    } else if (c < 2 * DI + DS) {
        *reinterpret_cast<float2*>(&g_Bm[r * DS + (c - 2 * DI)]) = make_float2(siluf(v0), siluf(v1));
    } else if (c < 2 * DI + 2 * DS) {
        *reinterpret_cast<float2*>(&g_Cm[r * DS + (c - 2 * DI - DS)]) = make_float2(siluf(v0), siluf(v1));
    } else {
        int hh = c - (2 * DI + 2 * DS);
        *reinterpret_cast<float2*>(&g_dt[r * NH + hh]) =
            make_float2(softplusf(v0 + __ldg(&dtb[hh])), softplusf(v1 + __ldg(&dtb[hh + 1])));
    }
}

__global__ void k_inproj_mma(const float* __restrict__ W,
                             const float* __restrict__ bias,
                             const float* __restrict__ dt_bias,
                             int l) {
    extern __shared__ float smem[];
    float* sH = smem;                        // IPM x SH_STRIDE
    float* sW0 = sH + IPM * SH_STRIDE;       // 64 x SW_STRIDE
    float* sW1 = sW0 + 64 * SW_STRIDE;       // 64 x SW_STRIDE
    float* sBias = sW1 + 64 * SW_STRIDE;     // 384

    const int row0 = blockIdx.x * IPM;
    const int tid = threadIdx.x;
    const int w = tid >> 5, lane = tid & 31;
    const int g = lane >> 2, tq = lane & 3;
    const int mrow = (w & 3) * 16;           // m-stripe
    const int nhalf = (w >> 2) * 32;         // n-half of each 64-col chunk
    const float* Wl = W + (size_t)l * DM * DPROJ;
    const float* dtb = dt_bias + l * NH;

    const int wn = tid & 63, wkhi = tid >> 6;
    float wr[16];

    {
        int c = wn;  // chunk 0
#pragma unroll
        for (int i = 0; i < 16; i++)
            wr[i] = __ldg(&Wl[(size_t)(4 * i + wkhi) * DPROJ + c]);
    }
    for (int idx = tid; idx < IPM * 16; idx += 256) {
        int r = idx >> 4, kq = (idx & 15) * 4;
        float4 v = *reinterpret_cast<const float4*>(&g_h[(size_t)(row0 + r) * DM + kq]);
        *reinterpret_cast<float4*>(&sH[r * SH_STRIDE + kq]) = v;
    }
    for (int idx = tid; idx < 384; idx += 256)
        sBias[idx] = (idx < DPROJ) ? bias[l * DPROJ + idx] : 0.f;
#pragma unroll
    for (int i = 0; i < 16; i++)
        sW0[(4 * i + wkhi) * SW_STRIDE + wn] = wr[i];
    __syncthreads();

    const int rA0 = (mrow + g) * SH_STRIDE;
    const int rA1 = (mrow + g + 8) * SH_STRIDE;

    for (int chunk = 0; chunk < 6; chunk++) {
        float* sWc = (chunk & 1) ? sW1 : sW0;
        float* sWn = (chunk & 1) ? sW0 : sW1;

        if (chunk < 5) {
            int c = (chunk + 1) * 64 + wn;
            bool ok = c < DPROJ;
#pragma unroll
            for (int i = 0; i < 16; i++)
                wr[i] = ok ? __ldg(&Wl[(size_t)(4 * i + wkhi) * DPROJ + c]) : 0.f;
        }

        float fa[4][4];
#pragma unroll
        for (int nt = 0; nt < 4; nt++)
#pragma unroll
            for (int j = 0; j < 4; j++) fa[nt][j] = 0.f;

#pragma unroll
        for (int k0 = 0; k0 < 64; k0 += 8) {
            unsigned ahi[4], alo[4];
            sp32(sH[rA0 + k0 + tq],     ahi[0], alo[0]);
            sp32(sH[rA1 + k0 + tq],     ahi[1], alo[1]);
            sp32(sH[rA0 + k0 + tq + 4], ahi[2], alo[2]);
            sp32(sH[rA1 + k0 + tq + 4], ahi[3], alo[3]);
#pragma unroll
            for (int nt = 0; nt < 4; nt++) {
                unsigned bhi[2], blo[2];
                sp32(sWc[(k0 + tq) * SW_STRIDE + nhalf + nt * 8 + g],     bhi[0], blo[0]);
                sp32(sWc[(k0 + tq + 4) * SW_STRIDE + nhalf + nt * 8 + g], bhi[1], blo[1]);
                mma_tf32(fa[nt], ahi, bhi);
                mma_tf32(fa[nt], ahi, blo);
                mma_tf32(fa[nt], alo, bhi);
            }
        }

#pragma unroll
        for (int nt = 0; nt < 4; nt++) {
            int cg = chunk * 64 + nhalf + nt * 8 + 2 * tq;
            if (cg >= DPROJ) continue;
            float b0v = sBias[cg], b1v = sBias[cg + 1];
            int r0 = row0 + mrow + g;
            ip_store(r0,     cg, fa[nt][0] + b0v, fa[nt][1] + b1v, dtb);
            ip_store(r0 + 8, cg, fa[nt][2] + b0v, fa[nt][3] + b1v, dtb);
        }

        if (chunk < 5) {
#pragma unroll
            for (int i = 0; i < 16; i++)
                sWn[(4 * i + wkhi) * SW_STRIDE + wn] = wr[i];
            __syncthreads();
        }
    }
}

// ================= K3: per-chunk summary (R13 per-head, validated) =======
#define CS_STRIDE 34
__global__ void k_chunk_summary(const float* __restrict__ A_log, int l) {
    const int bx = blockIdx.x;
    const int ch = bx & (NCH - 1);
    const int h  = (bx >> 7) & 3;
    const int b  = bx >> 9;
    const size_t base = (size_t)b * L_ + (size_t)ch * Q;
    __shared__ __align__(16) float sX[Q * CS_STRIDE];
    __shared__ __align__(16) float sB[Q * CS_STRIDE];
    __shared__ float sla[Q], sw_[Q], sdt[Q];
    const int tid = threadIdx.x;               // 256 threads

    for (int idx = tid; idx < Q * 8; idx += 256) {
        int s = idx >> 3, jq = (idx & 7) * 4;
        float4 xv = *reinterpret_cast<const float4*>(&g_X [(base + s) * DI + h * HD + jq]);
        float4 bv = *reinterpret_cast<const float4*>(&g_Bm[(base + s) * DS + jq]);
        sX[s * CS_STRIDE + jq]     = xv.x; sX[s * CS_STRIDE + jq + 1] = xv.y;
        sX[s * CS_STRIDE + jq + 2] = xv.z; sX[s * CS_STRIDE + jq + 3] = xv.w;
        sB[s * CS_STRIDE + jq]     = bv.x; sB[s * CS_STRIDE + jq + 1] = bv.y;
        sB[s * CS_STRIDE + jq + 2] = bv.z; sB[s * CS_STRIDE + jq + 3] = bv.w;
    }
    if (tid < Q) sdt[tid] = g_dt[(base + tid) * NH + h];
    __syncthreads();

    const float A = -expf(A_log[l * NH + h]);
    if (tid < Q) {
        float v = sdt[tid] * A;
#pragma unroll
        for (int o = 1; o < 32; o <<= 1) {
            float u = __shfl_up_sync(0xffffffffu, v, o);
            if ((tid & 31) >= o) v += u;
        }
        sla[tid] = v;
    }
    __syncthreads();
    if (tid >= 32 && tid < 64) sla[tid] += sla[31];
    __syncthreads();
    const float laQ = sla[Q - 1];
    if (tid < Q) {
        g_la[(base + tid) * NH + h] = sla[tid];
        sw_[tid] = sdt[tid] * __expf(laQ - sla[tid]);
    }
    __syncthreads();
    for (int idx = tid; idx < Q * HD; idx += 256) {
        int s = idx >> 5;
        sX[s * CS_STRIDE + (idx & 31)] *= sw_[s];
    }
    __syncthreads();

    const int p0 = (tid >> 4) * 2, n0 = (tid & 15) * 2;
    float a00 = 0.f, a01 = 0.f, a10 = 0.f, a11 = 0.f;
#pragma unroll 8
    for (int s = 0; s < Q; s++) {
        float2 xv = *reinterpret_cast<const float2*>(&sX[s * CS_STRIDE + p0]);
        float2 bv = *reinterpret_cast<const float2*>(&sB[s * CS_STRIDE + n0]);
        a00 += xv.x * bv.x; a01 += xv.x * bv.y;
        a10 += xv.y * bv.x; a11 += xv.y * bv.y;
    }
    float* dst = &g_Sd[(size_t)bx * 1024];
    *reinterpret_cast<float2*>(&dst[p0 * 32 + n0])       = make_float2(a00, a01);
    *reinterpret_cast<float2*>(&dst[(p0 + 1) * 32 + n0]) = make_float2(a10, a11);
    if (tid == 0) g_aQ[bx] = __expf(laQ);
}

// ================= K4a: segment-local scan (MLP=8 prefetch) ==============
__global__ void k_scan_seg() {
    const int blk = blockIdx.x;
    const int bh = blk >> 4, seg = blk & (NSEG - 1);
    const int tid = threadIdx.x;       // 1024
    const size_t cbase = (size_t)bh * NCH + seg * CPS;
    float aq[CPS], sd[CPS];
#pragma unroll
    for (int j = 0; j < CPS; j++) aq[j] = __ldg(&g_aQ[cbase + j]);
#pragma unroll
    for (int j = 0; j < CPS; j++) sd[j] = g_Sd[(cbase + j) * 1024 + tid];
    float hloc = 0.f;
#pragma unroll
    for (int j = 0; j < CPS; j++) {
        g_h0[(cbase + j) * 1024 + tid] = hloc;
        hloc = aq[j] * hloc + sd[j];
    }
    g_segS[(size_t)blk * 1024 + tid] = hloc;
    if (tid == 0) {
        float p = 1.f;
#pragma unroll
        for (int j = 0; j < CPS; j++) p *= aq[j];
        g_segA[blk] = p;
    }
}

// ================= K4b: top-level segment scan (MLP=16 prefetch) =========
__global__ void k_scan_top() {
    const int bh = blockIdx.x;         // 64 blocks
    const int tid = threadIdx.x;       // 1024
    float sa[NSEG], ss[NSEG];
#pragma unroll
    for (int seg = 0; seg < NSEG; seg++) sa[seg] = __ldg(&g_segA[bh * NSEG + seg]);
#pragma unroll
    for (int seg = 0; seg < NSEG; seg++)
        ss[seg] = g_segS[((size_t)bh * NSEG + seg) * 1024 + tid];
    float carry = 0.f;
#pragma unroll
    for (int seg = 0; seg < NSEG; seg++) {
        g_segIn[((size_t)bh * NSEG + seg) * 1024 + tid] = carry;
        carry = sa[seg] * carry + ss[seg];
    }
}

// ================= K5: chunk output via tf32 MMA (fb epilogue) ===========
#define SXO 40   // ≡8 mod 32
#define SBC 36   // ≡4 mod 32
#define SGS 68   // ≡4 mod 32
#define CO_SMEM ((Q*SXO + Q*SBC + Q*SBC + HD*SBC + Q*SGS + 3*Q) * 4)

__global__ void k_chunk_output_mma(const float* __restrict__ Dp, int l) {
    extern __shared__ float sm[];
    float* sX  = sm;                     // [64][SXO]
    float* sB  = sX + Q * SXO;           // [64][SBC]
    float* sC  = sB + Q * SBC;           // [64][SBC]
    float* sh0 = sC + Q * SBC;           // [32][SBC]
    float* sG  = sh0 + HD * SBC;         // [64][SGS]
    float* sla = sG + Q * SGS;           // [64]
    float* sdt = sla + Q;                // [64]
    float* sE  = sdt + Q;                // [64]

    const int bx = blockIdx.x;
    const int ch = bx & (NCH - 1);
    const int h  = (bx >> 7) & 3;
    const int b  = bx >> 9;
    const int bhIdx = b * NH + h;
    const size_t base = (size_t)b * L_ + (size_t)ch * Q;
    const int tid = threadIdx.x;         // 256
    const int w = tid >> 5, lane = tid & 31;
    const int g = lane >> 2, tq = lane & 3;
    const int mrow = (w & 3) * 16;

    for (int idx = tid; idx < Q * 8; idx += 256) {
        int s = idx >> 3, jq = (idx & 7) * 4;
        float4 xv = *reinterpret_cast<const float4*>(&g_X [(base + s) * DI + h * HD + jq]);
        float4 bv = *reinterpret_cast<const float4*>(&g_Bm[(base + s) * DS + jq]);
        float4 cv = *reinterpret_cast<const float4*>(&g_Cm[(base + s) * DS + jq]);
        *reinterpret_cast<float4*>(&sX[s * SXO + jq]) = xv;
        *reinterpret_cast<float4*>(&sB[s * SBC + jq]) = bv;
        *reinterpret_cast<float4*>(&sC[s * SBC + jq]) = cv;
    }
    if (tid < Q) {
        float la = g_la[(base + tid) * NH + h];
        sla[tid] = la;
        sdt[tid] = g_dt[(base + tid) * NH + h];
        sE[tid] = __expf(la);
    }
    {
        float p = 1.f;
        int j0 = ch & (CPS - 1);
        size_t cb = (size_t)bhIdx * NCH + (size_t)(ch & ~(CPS - 1));
        for (int j = 0; j < j0; j++) p *= __ldg(&g_aQ[cb + j]);
        const int idx4 = tid * 4;
        const int seg = ch >> 3;
        const size_t sio = ((size_t)bhIdx * NSEG + seg) * 1024;
        float4 a = *reinterpret_cast<const float4*>(&g_h0[(size_t)bx * 1024 + idx4]);
        float4 si = *reinterpret_cast<const float4*>(&g_segIn[sio + idx4]);
        int pr = idx4 >> 5, j = idx4 & 31;
        float4 r;
        r.x = a.x + p * si.x; r.y = a.y + p * si.y;
        r.z = a.z + p * si.z; r.w = a.w + p * si.w;
        *reinterpret_cast<float4*>(&sh0[pr * SBC + j]) = r;
    }
    __syncthreads();

    // ---- Phase 1: G = C . B^T ----
    const int shalf = (w >> 2) * 32;
    float ga[4][4];
#pragma unroll
    for (int nt = 0; nt < 4; nt++)
#pragma unroll
        for (int j = 0; j < 4; j++) ga[nt][j] = 0.f;

#pragma unroll
    for (int k0 = 0; k0 < 32; k0 += 8) {
        unsigned ahi[4], alo[4];
        sp32(sC[(mrow + g) * SBC + k0 + tq],         ahi[0], alo[0]);
        sp32(sC[(mrow + g + 8) * SBC + k0 + tq],     ahi[1], alo[1]);
        sp32(sC[(mrow + g) * SBC + k0 + tq + 4],     ahi[2], alo[2]);
        sp32(sC[(mrow + g + 8) * SBC + k0 + tq + 4], ahi[3], alo[3]);
#pragma unroll
        for (int nt = 0; nt < 4; nt++) {
            int sc = shalf + nt * 8 + g;
            unsigned bhi[2], blo[2];
            sp32(sB[sc * SBC + k0 + tq],     bhi[0], blo[0]);
            sp32(sB[sc * SBC + k0 + tq + 4], bhi[1], blo[1]);
            mma_tf32(ga[nt], ahi, bhi);
            mma_tf32(ga[nt], ahi, blo);
            mma_tf32(ga[nt], alo, bhi);
        }
    }

    // ---- Phase 2: mask+exp into sG ----
#pragma unroll
    for (int nt = 0; nt < 4; nt++) {
        int s0 = shalf + nt * 8 + 2 * tq;
        int t0 = mrow + g, t1 = mrow + g + 8;
        float la0 = sla[t0], la1 = sla[t1];
        float d0 = sdt[s0], d1 = sdt[s0 + 1];
        float ls0 = sla[s0], ls1 = sla[s0 + 1];
        sG[t0 * SGS + s0]     = (s0 <= t0)     ? ga[nt][0] * d0 * __expf(la0 - ls0) : 0.f;
        sG[t0 * SGS + s0 + 1] = (s0 + 1 <= t0) ? ga[nt][1] * d1 * __expf(la0 - ls1) : 0.f;
        sG[t1 * SGS + s0]     = (s0 <= t1)     ? ga[nt][2] * d0 * __expf(la1 - ls0) : 0.f;
        sG[t1 * SGS + s0 + 1] = (s0 + 1 <= t1) ? ga[nt][3] * d1 * __expf(la1 - ls1) : 0.f;
    }
    __syncthreads();

    // ---- Phase 3: fa = G.X (k=64); fb = C.h0^T (k=32) ----
    const int phalf = (w >> 2) * 16;
    float fa[2][4], fb[2][4];
#pragma unroll
    for (int nt = 0; nt < 2; nt++)
#pragma unroll
        for (int j = 0; j < 4; j++) { fa[nt][j] = 0.f; fb[nt][j] = 0.f; }

#pragma unroll
    for (int k0 = 0; k0 < Q; k0 += 8) {
        unsigned ahi[4], alo[4];
        sp32(sG[(mrow + g) * SGS + k0 + tq],         ahi[0], alo[0]);
        sp32(sG[(mrow + g + 8) * SGS + k0 + tq],     ahi[1], alo[1]);
        sp32(sG[(mrow + g) * SGS + k0 + tq + 4],     ahi[2], alo[2]);
        sp32(sG[(mrow + g + 8) * SGS + k0 + tq + 4], ahi[3], alo[3]);
#pragma unroll
        for (int nt = 0; nt < 2; nt++) {
            int pc = phalf + nt * 8 + g;
            unsigned bhi[2], blo[2];
            sp32(sX[(k0 + tq) * SXO + pc],     bhi[0], blo[0]);
            sp32(sX[(k0 + tq + 4) * SXO + pc], bhi[1], blo[1]);
            mma_tf32(fa[nt], ahi, bhi);
            mma_tf32(fa[nt], ahi, blo);
            mma_tf32(fa[nt], alo, bhi);
        }
    }
#pragma unroll
    for (int k0 = 0; k0 < 32; k0 += 8) {
        unsigned ahi[4], alo[4];
        sp32(sC[(mrow + g) * SBC + k0 + tq],         ahi[0], alo[0]);
        sp32(sC[(mrow + g + 8) * SBC + k0 + tq],     ahi[1], alo[1]);
        sp32(sC[(mrow + g) * SBC + k0 + tq + 4],     ahi[2], alo[2]);
        sp32(sC[(mrow + g + 8) * SBC + k0 + tq + 4], ahi[3], alo[3]);
#pragma unroll
        for (int nt = 0; nt < 2; nt++) {
            int pc = phalf + nt * 8 + g;
            unsigned bhi[2], blo[2];
            sp32(sh0[pc * SBC + k0 + tq],     bhi[0], blo[0]);
            sp32(sh0[pc * SBC + k0 + tq + 4], bhi[1], blo[1]);
            mma_tf32(fb[nt], ahi, bhi);
            mma_tf32(fb[nt], ahi, blo);
            mma_tf32(fb[nt], alo, bhi);
        }
    }

    // ---- Epilogue: y = (fa + E_t*fb + D*x) * z ----
    const float Dh = Dp[l * NH + h];
    const float E0 = sE[mrow + g], E1 = sE[mrow + g + 8];
#pragma unroll
    for (int nt = 0; nt < 2; nt++) {
        int pc = phalf + nt * 8 + 2 * tq;
        {
            int t = mrow + g;
            size_t o = (base + t) * DI + h * HD + pc;
            float2 z = *reinterpret_cast<const float2*>(&g_Z[o]);
            float2 r;
            r.x = (fa[nt][0] + E0 * fb[nt][0] + Dh * sX[t * SXO + pc]) * z.x;
            r.y = (fa[nt][1] + E0 * fb[nt][1] + Dh * sX[t * SXO + pc + 1]) * z.y;
            *reinterpret_cast<float2*>(&g_y[o]) = r;
        }
        {
            int t = mrow + g + 8;
            size_t o = (base + t) * DI + h * HD + pc;
            float2 z = *reinterpret_cast<const float2*>(&g_Z[o]);
            float2 r;
            r.x = (fa[nt][2] + E1 * fb[nt][2] + Dh * sX[t * SXO + pc]) * z.x;
            r.y = (fa[nt][3] + E1 * fb[nt][3] + Dh * sX[t * SXO + pc + 1]) * z.y;
            *reinterpret_cast<float2*>(&g_y[o]) = r;
        }
    }
}

// ================= K6: out_proj via tf32 MMA + residual (OPM=64) =========
#define OPM 64
#define SY_STRIDE 132    // ≡4 mod 32
#define OP_SMEM ((OPM * SY_STRIDE + DI * SW_STRIDE + 64) * 4)
__global__ void k_outproj_mma(const float* __restrict__ Wo,
                              const float* __restrict__ bo,
                              int l) {
    extern __shared__ float smem[];
    float* sY = smem;
    float* sW2 = sY + OPM * SY_STRIDE;
    float* sB2 = sW2 + DI * SW_STRIDE;

    const int row0 = blockIdx.x * OPM;
    const int tid = threadIdx.x;
    const int w = tid >> 5, lane = tid & 31;
    const int g = lane >> 2, tq = lane & 3;
    const int mrow = (w & 3) * 16;
    const int nhalf = (w >> 2) * 32;
    const float* Wl = Wo + (size_t)l * DI * DM;

    for (int idx = tid; idx < OPM * 32; idx += 256) {
        int r = idx >> 5, kq = (idx & 31) * 4;
        float4 v = *reinterpret_cast<const float4*>(&g_y[(size_t)(row0 + r) * DI + kq]);
        *reinterpret_cast<float4*>(&sY[r * SY_STRIDE + kq]) = v;
    }
    for (int idx = tid; idx < DI * 16; idx += 256) {
        int k = idx >> 4, nq = (idx & 15) * 4;
        float4 v = *reinterpret_cast<const float4*>(&Wl[(size_t)k * DM + nq]);
        *reinterpret_cast<float4*>(&sW2[k * SW_STRIDE + nq]) = v;
    }
    if (tid < 64) sB2[tid] = bo[l * DM + tid];
    __syncthreads();

    const int rA0 = (mrow + g) * SY_STRIDE;
    const int rA1 = (mrow + g + 8) * SY_STRIDE;

    float fa[4][4];
#pragma unroll
    for (int nt = 0; nt < 4; nt++)
#pragma unroll
        for (int j = 0; j < 4; j++) fa[nt][j] = 0.f;

#pragma unroll 4
    for (int k0 = 0; k0 < DI; k0 += 8) {
        unsigned ahi[4], alo[4];
        sp32(sY[rA0 + k0 + tq],     ahi[0], alo[0]);
        sp32(sY[rA1 + k0 + tq],     ahi[1], alo[1]);
        sp32(sY[rA0 + k0 + tq + 4], ahi[2], alo[2]);
        sp32(sY[rA1 + k0 + tq + 4], ahi[3], alo[3]);
#pragma unroll
        for (int nt = 0; nt < 4; nt++) {
            unsigned bhi[2], blo[2];
            sp32(sW2[(k0 + tq) * SW_STRIDE + nhalf + nt * 8 + g],     bhi[0], blo[0]);
            sp32(sW2[(k0 + tq + 4) * SW_STRIDE + nhalf + nt * 8 + g], bhi[1], blo[1]);
            mma_tf32(fa[nt], ahi, bhi);
            mma_tf32(fa[nt], ahi, blo);
            mma_tf32(fa[nt], alo, bhi);
        }
    }

#pragma unroll
    for (int nt = 0; nt < 4; nt++) {
        int c = nhalf + nt * 8 + 2 * tq;
        float bc0 = sB2[c], bc1 = sB2[c + 1];
#pragma unroll
        for (int half = 0; half < 2; half++) {
            int r = row0 + mrow + g + half * 8;
            size_t o = (size_t)r * DM + c;
            float2 hv = *reinterpret_cast<float2*>(&g_h[o]);
            hv.x += fa[nt][half * 2 + 0] + bc0;
            hv.y += fa[nt][half * 2 + 1] + bc1;
            *reinterpret_cast<float2*>(&g_h[o]) = hv;
        }
    }
}

// ================= K7a: pooling partial sums =================
__global__ void k_pool_a() {
    const int b = blockIdx.x >> 4, seg = blockIdx.x & 15;
    const int tid = threadIdx.x;   // 256
    const int d = tid & 63, part = tid >> 6;
    double s = 0.0;
    for (int ll = seg * 512 + part; ll < (seg + 1) * 512; ll += 4)
        s += (double)g_h[((size_t)b * L_ + ll) * DM + d];
    __shared__ double red[4][64];
    red[part][d] = s;
    __syncthreads();
    if (tid < 64)
        g_pool[((size_t)b * 16 + seg) * DM + tid] =
            red[0][tid] + red[1][tid] + red[2][tid] + red[3][tid];
}

// ================= K7b: combine + classifier =================
__global__ void k_pool_cls(const float* __restrict__ cW,
                           const float* __restrict__ cb,
                           float* __restrict__ out) {
    const int b = blockIdx.x;
    const int tid = threadIdx.x;   // 64
    __shared__ double pooled[64];
    double s = 0.0;
    for (int seg = 0; seg < 16; seg++)
        s += g_pool[((size_t)b * 16 + seg) * DM + tid];
    pooled[tid] = s / (double)L_;
    __syncthreads();
    if (tid < OUT_) {
        double acc = (double)cb[tid];
        for (int dd = 0; dd < DM; dd++)
            acc += pooled[dd] * (double)cW[dd * OUT_ + tid];
        out[b * OUT_ + tid] = (float)acc;
    }
}

// ================= launch =================
extern "C" void kernel_launch(void* const* d_in, const int* in_sizes, int n_in,
                              void* d_out, int out_size) {
    const float* x        = (const float*)d_in[0];
    const float* W_in     = (const float*)d_in[1];
    const float* b_in     = (const float*)d_in[2];
    const float* in_proj_W= (const float*)d_in[3];
    const float* in_proj_b= (const float*)d_in[4];
    const float* A_log    = (const float*)d_in[5];
    const float* Dp       = (const float*)d_in[6];
    const float* dt_bias  = (const float*)d_in[7];
    const float* out_proj_W = (const float*)d_in[8];
    const float* out_proj_b = (const float*)d_in[9];
    const float* cls_W    = (const float*)d_in[10];
    const float* cls_b    = (const float*)d_in[11];
    float* out = (float*)d_out;

    cudaFuncSetAttribute(k_inproj_mma, cudaFuncAttributeMaxDynamicSharedMemorySize, IP_SMEM);
    cudaFuncSetAttribute(k_outproj_mma, cudaFuncAttributeMaxDynamicSharedMemorySize, OP_SMEM);
    cudaFuncSetAttribute(k_chunk_output_mma, cudaFuncAttributeMaxDynamicSharedMemorySize, CO_SMEM);

    k_linear_in<<<BL / 16, 256>>>(x, W_in, b_in);
    for (int l = 0; l < NL; l++) {
        k_inproj_mma<<<BL / IPM, 256, IP_SMEM>>>(in_proj_W, in_proj_b, dt_bias, l);
        k_chunk_summary<<<B_ * NH * NCH, 256>>>(A_log, l);
        k_scan_seg<<<B_ * NH * NSEG, 1024>>>();
        k_scan_top<<<B_ * NH, 1024>>>();
        k_chunk_output_mma<<<B_ * NH * NCH, 256, CO_SMEM>>>(Dp, l);
        k_outproj_mma<<<BL / OPM, 256, OP_SMEM>>>(out_proj_W, out_proj_b, l);
    }
    k_pool_a<<<B_ * 16, 256>>>();
    k_pool_cls<<<B_, 64>>>(cls_W, cls_b, out);
}

// round 17
// speedup vs baseline: 1.3000x; 1.0154x over previous
#include <cuda_runtime.h>
#include <cuda_bf16.h>
#include <cstdint>

// ---------------- problem constants ----------------
#define B_     16
#define L_     8192
#define IN_    57
#define DM     64
#define DS     32
#define HD     32
#define NH     4
#define DI     128          // EXP*DM
#define DPROJ  324          // 2*DI + 2*DS + NH
#define NL     2
#define OUT_   6
#define Q      64           // chunk length
#define NCH    (L_ / Q)     // 128 chunks
#define NSEG   16           // scan segments
#define CPS    (NCH / NSEG) // 8 chunks per segment
#define BL     (B_ * L_)    // 131072 rows

// ---------------- scratch (device globals; allocation-free) ----------------
__device__ float g_h [BL * DM];
__device__ float g_X [BL * DI];
__device__ float g_Z [BL * DI];
__device__ float g_y [BL * DI];
__device__ float g_Bm[BL * DS];
__device__ float g_Cm[BL * DS];
__device__ float g_dt[BL * NH];
__device__ float g_la[BL * NH];
__device__ float g_Sd[B_ * NH * NCH * HD * DS];    // chunk delta states
__device__ float g_h0[B_ * NH * NCH * HD * DS];    // segment-local entry states
__device__ float g_aQ[B_ * NH * NCH];              // chunk total decay
__device__ float g_segS[B_ * NH * NSEG * HD * DS]; // segment delta states
__device__ float g_segA[B_ * NH * NSEG];           // segment decay product
__device__ float g_segIn[B_ * NH * NSEG * HD * DS];// segment entry states
__device__ double g_pool[B_ * 16 * DM];

// ---------------- helpers ----------------
__device__ __forceinline__ float siluf(float v) { return v / (1.f + __expf(-v)); }
__device__ __forceinline__ float softplusf(float v) { return (v > 20.f) ? v : log1pf(__expf(v)); }

__device__ __forceinline__ unsigned cvt_tf32(float f) {
    unsigned u; asm("cvt.rna.tf32.f32 %0, %1;" : "=r"(u) : "f"(f)); return u;
}
__device__ __forceinline__ void sp32(float v, unsigned& h, unsigned& l) {
    h = cvt_tf32(v);
    l = cvt_tf32(v - __uint_as_float(h));
}
__device__ __forceinline__ void mma_tf32(float* d, const unsigned* a, const unsigned* b) {
    asm volatile("mma.sync.aligned.m16n8k8.row.col.f32.tf32.tf32.f32 "
                 "{%0,%1,%2,%3},{%4,%5,%6,%7},{%8,%9},{%0,%1,%2,%3};"
                 : "+f"(d[0]), "+f"(d[1]), "+f"(d[2]), "+f"(d[3])
                 : "r"(a[0]), "r"(a[1]), "r"(a[2]), "r"(a[3]),
                   "r"(b[0]), "r"(b[1]));
}

// ================= K1: linear_in  h = x @ W_in + b_in =================
__global__ void k_linear_in(const float* __restrict__ x,
                            const float* __restrict__ W,
                            const float* __restrict__ bias) {
    const int row0 = blockIdx.x * 16;
    __shared__ float sx[16][IN_ + 1];
    const int tid = threadIdx.x;
    for (int idx = tid; idx < 16 * IN_; idx += 256) {
        int r = idx / IN_, k = idx % IN_;
        sx[r][k] = x[(size_t)(row0 + r) * IN_ + k];
    }
    __syncthreads();
    const int c = tid & 63, q = tid >> 6;
    float bc = bias[c];
    float acc[4] = {bc, bc, bc, bc};
    for (int k = 0; k < IN_; k++) {
        float wv = __ldg(&W[k * DM + c]);
#pragma unroll
        for (int j = 0; j < 4; j++) acc[j] += sx[q * 4 + j][k] * wv;
    }
#pragma unroll
    for (int j = 0; j < 4; j++)
        g_h[(size_t)(row0 + q * 4 + j) * DM + c] = acc[j];
}

// ================= K2: in_proj via tf32 MMA (IPM=64, double-buffered W) ==
#define IPM 64
#define SH_STRIDE 68     // ≡4 mod 32: A-operand conflict-free
#define SW_STRIDE 72     // ≡8 mod 32: B-operand conflict-free
#define IP_SMEM ((IPM * SH_STRIDE + 2 * 64 * SW_STRIDE + 384) * 4)

__device__ __forceinline__ void ip_store(int row, int c, float v0, float v1,
                                         const float* __restrict__ dtb) {
    size_t r = (size_t)row;
    if (c < DI) {
        *reinterpret_cast<float2*>(&g_Z[r * DI + c]) = make_float2(siluf(v0), siluf(v1));
    } else if (c < 2 * DI) {
        *reinterpret_cast<float2*>(&g_X[r * DI + (c - DI)]) = make_float2(siluf(v0), siluf(v1));
    } else if (c < 2 * DI + DS) {
        *reinterpret_cast<float2*>(&g_Bm[r * DS + (c - 2 * DI)]) = make_float2(siluf(v0), siluf(v1));
    } else if (c < 2 * DI + 2 * DS) {
        *reinterpret_cast<float2*>(&g_Cm[r * DS + (c - 2 * DI - DS)]) = make_float2(siluf(v0), siluf(v1));
    } else {
        int hh = c - (2 * DI + 2 * DS);
        *reinterpret_cast<float2*>(&g_dt[r * NH + hh]) =
            make_float2(softplusf(v0 + __ldg(&dtb[hh])), softplusf(v1 + __ldg(&dtb[hh + 1])));
    }
}

__global__ void k_inproj_mma(const float* __restrict__ W,
                             const float* __restrict__ bias,
                             const float* __restrict__ dt_bias,
                             int l) {
    extern __shared__ float smem[];
    float* sH = smem;                        // IPM x SH_STRIDE
    float* sW0 = sH + IPM * SH_STRIDE;       // 64 x SW_STRIDE
    float* sW1 = sW0 + 64 * SW_STRIDE;       // 64 x SW_STRIDE
    float* sBias = sW1 + 64 * SW_STRIDE;     // 384

    const int row0 = blockIdx.x * IPM;
    const int tid = threadIdx.x;
    const int w = tid >> 5, lane = tid & 31;
    const int g = lane >> 2, tq = lane & 3;
    const int mrow = (w & 3) * 16;           // m-stripe
    const int nhalf = (w >> 2) * 32;         // n-half of each 64-col chunk
    const float* Wl = W + (size_t)l * DM * DPROJ;
    const float* dtb = dt_bias + l * NH;

    const int wn = tid & 63, wkhi = tid >> 6;
    float wr[16];

    {
        int c = wn;  // chunk 0
#pragma unroll
        for (int i = 0; i < 16; i++)
            wr[i] = __ldg(&Wl[(size_t)(4 * i + wkhi) * DPROJ + c]);
    }
    for (int idx = tid; idx < IPM * 16; idx += 256) {
        int r = idx >> 4, kq = (idx & 15) * 4;
        float4 v = *reinterpret_cast<const float4*>(&g_h[(size_t)(row0 + r) * DM + kq]);
        *reinterpret_cast<float4*>(&sH[r * SH_STRIDE + kq]) = v;
    }
    for (int idx = tid; idx < 384; idx += 256)
        sBias[idx] = (idx < DPROJ) ? bias[l * DPROJ + idx] : 0.f;
#pragma unroll
    for (int i = 0; i < 16; i++)
        sW0[(4 * i + wkhi) * SW_STRIDE + wn] = wr[i];
    __syncthreads();

    const int rA0 = (mrow + g) * SH_STRIDE;
    const int rA1 = (mrow + g + 8) * SH_STRIDE;

    for (int chunk = 0; chunk < 6; chunk++) {
        float* sWc = (chunk & 1) ? sW1 : sW0;
        float* sWn = (chunk & 1) ? sW0 : sW1;

        if (chunk < 5) {
            int c = (chunk + 1) * 64 + wn;
            bool ok = c < DPROJ;
#pragma unroll
            for (int i = 0; i < 16; i++)
                wr[i] = ok ? __ldg(&Wl[(size_t)(4 * i + wkhi) * DPROJ + c]) : 0.f;
        }

        float fa[4][4];
#pragma unroll
        for (int nt = 0; nt < 4; nt++)
#pragma unroll
            for (int j = 0; j < 4; j++) fa[nt][j] = 0.f;

#pragma unroll
        for (int k0 = 0; k0 < 64; k0 += 8) {
            unsigned ahi[4], alo[4];
            sp32(sH[rA0 + k0 + tq],     ahi[0], alo[0]);
            sp32(sH[rA1 + k0 + tq],     ahi[1], alo[1]);
            sp32(sH[rA0 + k0 + tq + 4], ahi[2], alo[2]);
            sp32(sH[rA1 + k0 + tq + 4], ahi[3], alo[3]);
#pragma unroll
            for (int nt = 0; nt < 4; nt++) {
                unsigned bhi[2], blo[2];
                sp32(sWc[(k0 + tq) * SW_STRIDE + nhalf + nt * 8 + g],     bhi[0], blo[0]);
                sp32(sWc[(k0 + tq + 4) * SW_STRIDE + nhalf + nt * 8 + g], bhi[1], blo[1]);
                mma_tf32(fa[nt], ahi, bhi);
                mma_tf32(fa[nt], ahi, blo);
                mma_tf32(fa[nt], alo, bhi);
            }
        }

#pragma unroll
        for (int nt = 0; nt < 4; nt++) {
            int cg = chunk * 64 + nhalf + nt * 8 + 2 * tq;
            if (cg >= DPROJ) continue;
            float b0v = sBias[cg], b1v = sBias[cg + 1];
            int r0 = row0 + mrow + g;
            ip_store(r0,     cg, fa[nt][0] + b0v, fa[nt][1] + b1v, dtb);
            ip_store(r0 + 8, cg, fa[nt][2] + b0v, fa[nt][3] + b1v, dtb);
        }

        if (chunk < 5) {
#pragma unroll
            for (int i = 0; i < 16; i++)
                sWn[(4 * i + wkhi) * SW_STRIDE + wn] = wr[i];
            __syncthreads();
        }
    }
}

// ================= K3: per-chunk summary (R13 per-head, validated) =======
#define CS_STRIDE 34
__global__ void k_chunk_summary(const float* __restrict__ A_log, int l) {
    const int bx = blockIdx.x;
    const int ch = bx & (NCH - 1);
    const int h  = (bx >> 7) & 3;
    const int b  = bx >> 9;
    const size_t base = (size_t)b * L_ + (size_t)ch * Q;
    __shared__ __align__(16) float sX[Q * CS_STRIDE];
    __shared__ __align__(16) float sB[Q * CS_STRIDE];
    __shared__ float sla[Q], sw_[Q], sdt[Q];
    const int tid = threadIdx.x;               // 256 threads

    for (int idx = tid; idx < Q * 8; idx += 256) {
        int s = idx >> 3, jq = (idx & 7) * 4;
        float4 xv = *reinterpret_cast<const float4*>(&g_X [(base + s) * DI + h * HD + jq]);
        float4 bv = *reinterpret_cast<const float4*>(&g_Bm[(base + s) * DS + jq]);
        sX[s * CS_STRIDE + jq]     = xv.x; sX[s * CS_STRIDE + jq + 1] = xv.y;
        sX[s * CS_STRIDE + jq + 2] = xv.z; sX[s * CS_STRIDE + jq + 3] = xv.w;
        sB[s * CS_STRIDE + jq]     = bv.x; sB[s * CS_STRIDE + jq + 1] = bv.y;
        sB[s * CS_STRIDE + jq + 2] = bv.z; sB[s * CS_STRIDE + jq + 3] = bv.w;
    }
    if (tid < Q) sdt[tid] = g_dt[(base + tid) * NH + h];
    __syncthreads();

    const float A = -expf(A_log[l * NH + h]);
    if (tid < Q) {
        float v = sdt[tid] * A;
#pragma unroll
        for (int o = 1; o < 32; o <<= 1) {
            float u = __shfl_up_sync(0xffffffffu, v, o);
            if ((tid & 31) >= o) v += u;
        }
        sla[tid] = v;
    }
    __syncthreads();
    if (tid >= 32 && tid < 64) sla[tid] += sla[31];
    __syncthreads();
    const float laQ = sla[Q - 1];
    if (tid < Q) {
        g_la[(base + tid) * NH + h] = sla[tid];
        sw_[tid] = sdt[tid] * __expf(laQ - sla[tid]);
    }
    __syncthreads();
    for (int idx = tid; idx < Q * HD; idx += 256) {
        int s = idx >> 5;
        sX[s * CS_STRIDE + (idx & 31)] *= sw_[s];
    }
    __syncthreads();

    const int p0 = (tid >> 4) * 2, n0 = (tid & 15) * 2;
    float a00 = 0.f, a01 = 0.f, a10 = 0.f, a11 = 0.f;
#pragma unroll 8
    for (int s = 0; s < Q; s++) {
        float2 xv = *reinterpret_cast<const float2*>(&sX[s * CS_STRIDE + p0]);
        float2 bv = *reinterpret_cast<const float2*>(&sB[s * CS_STRIDE + n0]);
        a00 += xv.x * bv.x; a01 += xv.x * bv.y;
        a10 += xv.y * bv.x; a11 += xv.y * bv.y;
    }
    float* dst = &g_Sd[(size_t)bx * 1024];
    *reinterpret_cast<float2*>(&dst[p0 * 32 + n0])       = make_float2(a00, a01);
    *reinterpret_cast<float2*>(&dst[(p0 + 1) * 32 + n0]) = make_float2(a10, a11);
    if (tid == 0) g_aQ[bx] = __expf(laQ);
}

// ================= K4a: segment-local scan (MLP=8 prefetch) ==============
__global__ void k_scan_seg() {
    const int blk = blockIdx.x;
    const int bh = blk >> 4, seg = blk & (NSEG - 1);
    const int tid = threadIdx.x;       // 1024
    const size_t cbase = (size_t)bh * NCH + seg * CPS;
    float aq[CPS], sd[CPS];
#pragma unroll
    for (int j = 0; j < CPS; j++) aq[j] = __ldg(&g_aQ[cbase + j]);
#pragma unroll
    for (int j = 0; j < CPS; j++) sd[j] = g_Sd[(cbase + j) * 1024 + tid];
    float hloc = 0.f;
#pragma unroll
    for (int j = 0; j < CPS; j++) {
        g_h0[(cbase + j) * 1024 + tid] = hloc;
        hloc = aq[j] * hloc + sd[j];
    }
    g_segS[(size_t)blk * 1024 + tid] = hloc;
    if (tid == 0) {
        float p = 1.f;
#pragma unroll
        for (int j = 0; j < CPS; j++) p *= aq[j];
        g_segA[blk] = p;
    }
}

// ================= K4b: top-level segment scan (MLP=16 prefetch) =========
__global__ void k_scan_top() {
    const int bh = blockIdx.x;         // 64 blocks
    const int tid = threadIdx.x;       // 1024
    float sa[NSEG], ss[NSEG];
#pragma unroll
    for (int seg = 0; seg < NSEG; seg++) sa[seg] = __ldg(&g_segA[bh * NSEG + seg]);
#pragma unroll
    for (int seg = 0; seg < NSEG; seg++)
        ss[seg] = g_segS[((size_t)bh * NSEG + seg) * 1024 + tid];
    float carry = 0.f;
#pragma unroll
    for (int seg = 0; seg < NSEG; seg++) {
        g_segIn[((size_t)bh * NSEG + seg) * 1024 + tid] = carry;
        carry = sa[seg] * carry + ss[seg];
    }
}

// ================= K5: chunk output via tf32 MMA (causal tile-skip) ======
#define SXO 40   // ≡8 mod 32
#define SBC 36   // ≡4 mod 32
#define SGS 68   // ≡4 mod 32
#define CO_SMEM ((Q*SXO + Q*SBC + Q*SBC + HD*SBC + Q*SGS + 3*Q) * 4)

__global__ void k_chunk_output_mma(const float* __restrict__ Dp, int l) {
    extern __shared__ float sm[];
    float* sX  = sm;                     // [64][SXO]
    float* sB  = sX + Q * SXO;           // [64][SBC]
    float* sC  = sB + Q * SBC;           // [64][SBC]
    float* sh0 = sC + Q * SBC;           // [32][SBC]
    float* sG  = sh0 + HD * SBC;         // [64][SGS]
    float* sla = sG + Q * SGS;           // [64]
    float* sdt = sla + Q;                // [64]
    float* sE  = sdt + Q;                // [64]

    const int bx = blockIdx.x;
    const int ch = bx & (NCH - 1);
    const int h  = (bx >> 7) & 3;
    const int b  = bx >> 9;
    const int bhIdx = b * NH + h;
    const size_t base = (size_t)b * L_ + (size_t)ch * Q;
    const int tid = threadIdx.x;         // 256
    const int w = tid >> 5, lane = tid & 31;
    const int g = lane >> 2, tq = lane & 3;
    const int mrow = (w & 3) * 16;

    for (int idx = tid; idx < Q * 8; idx += 256) {
        int s = idx >> 3, jq = (idx & 7) * 4;
        float4 xv = *reinterpret_cast<const float4*>(&g_X [(base + s) * DI + h * HD + jq]);
        float4 bv = *reinterpret_cast<const float4*>(&g_Bm[(base + s) * DS + jq]);
        float4 cv = *reinterpret_cast<const float4*>(&g_Cm[(base + s) * DS + jq]);
        *reinterpret_cast<float4*>(&sX[s * SXO + jq]) = xv;
        *reinterpret_cast<float4*>(&sB[s * SBC + jq]) = bv;
        *reinterpret_cast<float4*>(&sC[s * SBC + jq]) = cv;
    }
    if (tid < Q) {
        float la = g_la[(base + tid) * NH + h];
        sla[tid] = la;
        sdt[tid] = g_dt[(base + tid) * NH + h];
        sE[tid] = __expf(la);
    }
    {
        float p = 1.f;
        int j0 = ch & (CPS - 1);
        size_t cb = (size_t)bhIdx * NCH + (size_t)(ch & ~(CPS - 1));
        for (int j = 0; j < j0; j++) p *= __ldg(&g_aQ[cb + j]);
        const int idx4 = tid * 4;
        const int seg = ch >> 3;
        const size_t sio = ((size_t)bhIdx * NSEG + seg) * 1024;
        float4 a = *reinterpret_cast<const float4*>(&g_h0[(size_t)bx * 1024 + idx4]);
        float4 si = *reinterpret_cast<const float4*>(&g_segIn[sio + idx4]);
        int pr = idx4 >> 5, j = idx4 & 31;
        float4 r;
        r.x = a.x + p * si.x; r.y = a.y + p * si.y;
        r.z = a.z + p * si.z; r.w = a.w + p * si.w;
        *reinterpret_cast<float4*>(&sh0[pr * SBC + j]) = r;
    }
    __syncthreads();

    // ---- Phase 1: G = C . B^T  (skip fully-masked causal tiles) ----
    const int shalf = (w >> 2) * 32;
    float ga[4][4];
#pragma unroll
    for (int nt = 0; nt < 4; nt++)
#pragma unroll
        for (int j = 0; j < 4; j++) ga[nt][j] = 0.f;

    if (shalf <= mrow + 15) {  // warp has at least one live tile
#pragma unroll
        for (int k0 = 0; k0 < 32; k0 += 8) {
            unsigned ahi[4], alo[4];
            sp32(sC[(mrow + g) * SBC + k0 + tq],         ahi[0], alo[0]);
            sp32(sC[(mrow + g + 8) * SBC + k0 + tq],     ahi[1], alo[1]);
            sp32(sC[(mrow + g) * SBC + k0 + tq + 4],     ahi[2], alo[2]);
            sp32(sC[(mrow + g + 8) * SBC + k0 + tq + 4], ahi[3], alo[3]);
#pragma unroll
            for (int nt = 0; nt < 4; nt++) {
                if (shalf + nt * 8 > mrow + 15) continue;   // tile fully masked -> G stays 0
                int sc = shalf + nt * 8 + g;
                unsigned bhi[2], blo[2];
                sp32(sB[sc * SBC + k0 + tq],     bhi[0], blo[0]);
                sp32(sB[sc * SBC + k0 + tq + 4], bhi[1], blo[1]);
                mma_tf32(ga[nt], ahi, bhi);
                mma_tf32(ga[nt], ahi, blo);
                mma_tf32(ga[nt], alo, bhi);
            }
        }
    }

    // ---- Phase 2: mask+exp into sG ----
#pragma unroll
    for (int nt = 0; nt < 4; nt++) {
        int s0 = shalf + nt * 8 + 2 * tq;
        int t0 = mrow + g, t1 = mrow + g + 8;
        float la0 = sla[t0], la1 = sla[t1];
        float d0 = sdt[s0], d1 = sdt[s0 + 1];
        float ls0 = sla[s0], ls1 = sla[s0 + 1];
        sG[t0 * SGS + s0]     = (s0 <= t0)     ? ga[nt][0] * d0 * __expf(la0 - ls0) : 0.f;
        sG[t0 * SGS + s0 + 1] = (s0 + 1 <= t0) ? ga[nt][1] * d1 * __expf(la0 - ls1) : 0.f;
        sG[t1 * SGS + s0]     = (s0 <= t1)     ? ga[nt][2] * d0 * __expf(la1 - ls0) : 0.f;
        sG[t1 * SGS + s0 + 1] = (s0 + 1 <= t1) ? ga[nt][3] * d1 * __expf(la1 - ls1) : 0.f;
    }
    __syncthreads();

    // ---- Phase 3: fa = G.X (k=64, skip zero G k-tiles); fb = C.h0^T ----
    const int phalf = (w >> 2) * 16;
    float fa[2][4], fb[2][4];
#pragma unroll
    for (int nt = 0; nt < 2; nt++)
#pragma unroll
        for (int j = 0; j < 4; j++) { fa[nt][j] = 0.f; fb[nt][j] = 0.f; }

#pragma unroll
    for (int k0 = 0; k0 < Q; k0 += 8) {
        if (k0 > mrow + 15) continue;   // G[mrow..mrow+15][k0..k0+7] all zero
        unsigned ahi[4], alo[4];
        sp32(sG[(mrow + g) * SGS + k0 + tq],         ahi[0], alo[0]);
        sp32(sG[(mrow + g + 8) * SGS + k0 + tq],     ahi[1], alo[1]);
        sp32(sG[(mrow + g) * SGS + k0 + tq + 4],     ahi[2], alo[2]);
        sp32(sG[(mrow + g + 8) * SGS + k0 + tq + 4], ahi[3], alo[3]);
#pragma unroll
        for (int nt = 0; nt < 2; nt++) {
            int pc = phalf + nt * 8 + g;
            unsigned bhi[2], blo[2];
            sp32(sX[(k0 + tq) * SXO + pc],     bhi[0], blo[0]);
            sp32(sX[(k0 + tq + 4) * SXO + pc], bhi[1], blo[1]);
            mma_tf32(fa[nt], ahi, bhi);
            mma_tf32(fa[nt], ahi, blo);
            mma_tf32(fa[nt], alo, bhi);
        }
    }
#pragma unroll
    for (int k0 = 0; k0 < 32; k0 += 8) {
        unsigned ahi[4], alo[4];
        sp32(sC[(mrow + g) * SBC + k0 + tq],         ahi[0], alo[0]);
        sp32(sC[(mrow + g + 8) * SBC + k0 + tq],     ahi[1], alo[1]);
        sp32(sC[(mrow + g) * SBC + k0 + tq + 4],     ahi[2], alo[2]);
        sp32(sC[(mrow + g + 8) * SBC + k0 + tq + 4], ahi[3], alo[3]);
#pragma unroll
        for (int nt = 0; nt < 2; nt++) {
            int pc = phalf + nt * 8 + g;
            unsigned bhi[2], blo[2];
            sp32(sh0[pc * SBC + k0 + tq],     bhi[0], blo[0]);
            sp32(sh0[pc * SBC + k0 + tq + 4], bhi[1], blo[1]);
            mma_tf32(fb[nt], ahi, bhi);
            mma_tf32(fb[nt], ahi, blo);
            mma_tf32(fb[nt], alo, bhi);
        }
    }

    // ---- Epilogue: y = (fa + E_t*fb + D*x) * z ----
    const float Dh = Dp[l * NH + h];
    const float E0 = sE[mrow + g], E1 = sE[mrow + g + 8];
#pragma unroll
    for (int nt = 0; nt < 2; nt++) {
        int pc = phalf + nt * 8 + 2 * tq;
        {
            int t = mrow + g;
            size_t o = (base + t) * DI + h * HD + pc;
            float2 z = *reinterpret_cast<const float2*>(&g_Z[o]);
            float2 r;
            r.x = (fa[nt][0] + E0 * fb[nt][0] + Dh * sX[t * SXO + pc]) * z.x;
            r.y = (fa[nt][1] + E0 * fb[nt][1] + Dh * sX[t * SXO + pc + 1]) * z.y;
            *reinterpret_cast<float2*>(&g_y[o]) = r;
        }
        {
            int t = mrow + g + 8;
            size_t o = (base + t) * DI + h * HD + pc;
            float2 z = *reinterpret_cast<const float2*>(&g_Z[o]);
            float2 r;
            r.x = (fa[nt][2] + E1 * fb[nt][2] + Dh * sX[t * SXO + pc]) * z.x;
            r.y = (fa[nt][3] + E1 * fb[nt][3] + Dh * sX[t * SXO + pc + 1]) * z.y;
            *reinterpret_cast<float2*>(&g_y[o]) = r;
        }
    }
}

// ================= K6: out_proj via tf32 MMA + residual (OPM=64) =========
#define OPM 64
#define SY_STRIDE 132    // ≡4 mod 32
#define OP_SMEM ((OPM * SY_STRIDE + DI * SW_STRIDE + 64) * 4)
__global__ void k_outproj_mma(const float* __restrict__ Wo,
                              const float* __restrict__ bo,
                              int l) {
    extern __shared__ float smem[];
    float* sY = smem;
    float* sW2 = sY + OPM * SY_STRIDE;
    float* sB2 = sW2 + DI * SW_STRIDE;

    const int row0 = blockIdx.x * OPM;
    const int tid = threadIdx.x;
    const int w = tid >> 5, lane = tid & 31;
    const int g = lane >> 2, tq = lane & 3;
    const int mrow = (w & 3) * 16;
    const int nhalf = (w >> 2) * 32;
    const float* Wl = Wo + (size_t)l * DI * DM;

    for (int idx = tid; idx < OPM * 32; idx += 256) {
        int r = idx >> 5, kq = (idx & 31) * 4;
        float4 v = *reinterpret_cast<const float4*>(&g_y[(size_t)(row0 + r) * DI + kq]);
        *reinterpret_cast<float4*>(&sY[r * SY_STRIDE + kq]) = v;
    }
    for (int idx = tid; idx < DI * 16; idx += 256) {
        int k = idx >> 4, nq = (idx & 15) * 4;
        float4 v = *reinterpret_cast<const float4*>(&Wl[(size_t)k * DM + nq]);
        *reinterpret_cast<float4*>(&sW2[k * SW_STRIDE + nq]) = v;
    }
    if (tid < 64) sB2[tid] = bo[l * DM + tid];
    __syncthreads();

    const int rA0 = (mrow + g) * SY_STRIDE;
    const int rA1 = (mrow + g + 8) * SY_STRIDE;

    float fa[4][4];
#pragma unroll
    for (int nt = 0; nt < 4; nt++)
#pragma unroll
        for (int j = 0; j < 4; j++) fa[nt][j] = 0.f;

#pragma unroll 4
    for (int k0 = 0; k0 < DI; k0 += 8) {
        unsigned ahi[4], alo[4];
        sp32(sY[rA0 + k0 + tq],     ahi[0], alo[0]);
        sp32(sY[rA1 + k0 + tq],     ahi[1], alo[1]);
        sp32(sY[rA0 + k0 + tq + 4], ahi[2], alo[2]);
        sp32(sY[rA1 + k0 + tq + 4], ahi[3], alo[3]);
#pragma unroll
        for (int nt = 0; nt < 4; nt++) {
            unsigned bhi[2], blo[2];
            sp32(sW2[(k0 + tq) * SW_STRIDE + nhalf + nt * 8 + g],     bhi[0], blo[0]);
            sp32(sW2[(k0 + tq + 4) * SW_STRIDE + nhalf + nt * 8 + g], bhi[1], blo[1]);
            mma_tf32(fa[nt], ahi, bhi);
            mma_tf32(fa[nt], ahi, blo);
            mma_tf32(fa[nt], alo, bhi);
        }
    }

#pragma unroll
    for (int nt = 0; nt < 4; nt++) {
        int c = nhalf + nt * 8 + 2 * tq;
        float bc0 = sB2[c], bc1 = sB2[c + 1];
#pragma unroll
        for (int half = 0; half < 2; half++) {
            int r = row0 + mrow + g + half * 8;
            size_t o = (size_t)r * DM + c;
            float2 hv = *reinterpret_cast<float2*>(&g_h[o]);
            hv.x += fa[nt][half * 2 + 0] + bc0;
            hv.y += fa[nt][half * 2 + 1] + bc1;
            *reinterpret_cast<float2*>(&g_h[o]) = hv;
        }
    }
}

// ================= K7a: pooling partial sums =================
__global__ void k_pool_a() {
    const int b = blockIdx.x >> 4, seg = blockIdx.x & 15;
    const int tid = threadIdx.x;   // 256
    const int d = tid & 63, part = tid >> 6;
    double s = 0.0;
    for (int ll = seg * 512 + part; ll < (seg + 1) * 512; ll += 4)
        s += (double)g_h[((size_t)b * L_ + ll) * DM + d];
    __shared__ double red[4][64];
    red[part][d] = s;
    __syncthreads();
    if (tid < 64)
        g_pool[((size_t)b * 16 + seg) * DM + tid] =
            red[0][tid] + red[1][tid] + red[2][tid] + red[3][tid];
}

// ================= K7b: combine + classifier =================
__global__ void k_pool_cls(const float* __restrict__ cW,
                           const float* __restrict__ cb,
                           float* __restrict__ out) {
    const int b = blockIdx.x;
    const int tid = threadIdx.x;   // 64
    __shared__ double pooled[64];
    double s = 0.0;
    for (int seg = 0; seg < 16; seg++)
        s += g_pool[((size_t)b * 16 + seg) * DM + tid];
    pooled[tid] = s / (double)L_;
    __syncthreads();
    if (tid < OUT_) {
        double acc = (double)cb[tid];
        for (int dd = 0; dd < DM; dd++)
            acc += pooled[dd] * (double)cW[dd * OUT_ + tid];
        out[b * OUT_ + tid] = (float)acc;
    }
}

// ================= launch =================
extern "C" void kernel_launch(void* const* d_in, const int* in_sizes, int n_in,
                              void* d_out, int out_size) {
    const float* x        = (const float*)d_in[0];
    const float* W_in     = (const float*)d_in[1];
    const float* b_in     = (const float*)d_in[2];
    const float* in_proj_W= (const float*)d_in[3];
    const float* in_proj_b= (const float*)d_in[4];
    const float* A_log    = (const float*)d_in[5];
    const float* Dp       = (const float*)d_in[6];
    const float* dt_bias  = (const float*)d_in[7];
    const float* out_proj_W = (const float*)d_in[8];
    const float* out_proj_b = (const float*)d_in[9];
    const float* cls_W    = (const float*)d_in[10];
    const float* cls_b    = (const float*)d_in[11];
    float* out = (float*)d_out;

    cudaFuncSetAttribute(k_inproj_mma, cudaFuncAttributeMaxDynamicSharedMemorySize, IP_SMEM);
    cudaFuncSetAttribute(k_outproj_mma, cudaFuncAttributeMaxDynamicSharedMemorySize, OP_SMEM);
    cudaFuncSetAttribute(k_chunk_output_mma, cudaFuncAttributeMaxDynamicSharedMemorySize, CO_SMEM);

    k_linear_in<<<BL / 16, 256>>>(x, W_in, b_in);
    for (int l = 0; l < NL; l++) {
        k_inproj_mma<<<BL / IPM, 256, IP_SMEM>>>(in_proj_W, in_proj_b, dt_bias, l);
        k_chunk_summary<<<B_ * NH * NCH, 256>>>(A_log, l);
        k_scan_seg<<<B_ * NH * NSEG, 1024>>>();
        k_scan_top<<<B_ * NH, 1024>>>();
        k_chunk_output_mma<<<B_ * NH * NCH, 256, CO_SMEM>>>(Dp, l);
        k_outproj_mma<<<BL / OPM, 256, OP_SMEM>>>(out_proj_W, out_proj_b, l);
    }
    k_pool_a<<<B_ * 16, 256>>>();
    k_pool_cls<<<B_, 64>>>(cls_W, cls_b, out);
}